// round 13
// baseline (speedup 1.0000x reference)
#include <cuda_runtime.h>
#include <cuda_bf16.h>
#include <cuda_fp16.h>
#include <mma.h>

using namespace nvcuda;

#define BATCH 64
#define SEQ   512
#define HID   512
#define GATES 2048
#define KIN   96
#define ODIM  128

#define NB_SCAN 128     // 64 layer-0 CTAs + 64 layer-1 CTAs
#define NT_SCAN 256
#define CCOLS   32
#define APADH   520     // 512+8 halfs: row stride 1040B ≡ 16B mod 128B
#define W1PADH  1032    // 1024+8 halfs: 2064B ≡ 16B mod 128B
#define SGP     36
// layer-0: As half[64][APADH] + Ws half[32][APADH]; sg(float) aliases As
#define L0_TOTAL_B   ((64 + 32) * APADH * 2)           // 99,840
// layer-1: Ws1 half[32][W1PADH] + As1 half[64][W1PADH]; sg(float) aliases As1
#define L1_TOTAL_B   ((32 + 64) * W1PADH * 2)          // 198,144
#define SCAN_SMEM_BYTES L1_TOTAL_B                     // 198,144 B (< 227 KB)

// ---------------- static device scratch ----------------
__device__ float  g_xproj[(size_t)BATCH * SEQ * GATES];
__device__ float  g_xcat[(size_t)BATCH * SEQ * KIN];
__device__ float  g_Wih0p[GATES * KIN];
__device__ __half g_Whh0h[GATES * HID];
__device__ __half g_Wih1h[GATES * HID];
__device__ __half g_Whh1h[GATES * HID];
__device__ float  g_biasP[2][GATES];
__device__ __half g_hbuf0[2][BATCH * HID];
__device__ __half g_hbuf1[2][BATCH * HID];
__device__ unsigned g_flags[NB_SCAN][32];   // per-CTA round flags, 128B apart

// ---------------- sync primitives ----------------
__device__ __forceinline__ unsigned ld_acquire_gpu(const unsigned* p) {
    unsigned v;
    asm volatile("ld.acquire.gpu.global.u32 %0, [%1];" : "=r"(v) : "l"(p) : "memory");
    return v;
}
__device__ __forceinline__ void st_release_gpu(unsigned* p, unsigned v) {
    asm volatile("st.release.gpu.global.u32 [%0], %1;" :: "l"(p), "r"(v) : "memory");
}

// all-to-all flag barrier: arrival = 1 release store to own flag; wait = warp 0
// polls all 128 flags in parallel. Monotonic rounds, replay-safe.
__device__ __forceinline__ void grid_barrier_round(unsigned round) {
    __syncthreads();
    if (threadIdx.x < 32) {
        if (threadIdx.x == 0)
            st_release_gpu(&g_flags[blockIdx.x][0], round);
        const int lane = threadIdx.x;
        bool ok;
        do {
            ok = true;
#pragma unroll
            for (int i = 0; i < NB_SCAN / 32; i++) {
                unsigned f = ld_acquire_gpu(&g_flags[lane + 32 * i][0]);
                ok &= ((int)(f - round) >= 0);
            }
        } while (!__all_sync(0xffffffffu, ok));
    }
    __syncthreads();
}

__device__ __forceinline__ float sigm(float x) { return 1.0f / (1.0f + expf(-x)); }

__device__ __forceinline__ float tf32_rna(float x) {
    unsigned u;
    asm("cvt.rna.tf32.f32 %0, %1;" : "=r"(u) : "f"(x));
    return __uint_as_float(u);
}

// ---------------- prep ----------------
__global__ void prep_kernel(const float* __restrict__ prim, const float* __restrict__ aux,
                            const float* __restrict__ Wih0, const float* __restrict__ Whh0,
                            const float* __restrict__ bih0, const float* __restrict__ bhh0,
                            const float* __restrict__ Wih1, const float* __restrict__ Whh1,
                            const float* __restrict__ bih1, const float* __restrict__ bhh1)
{
    size_t tid = (size_t)blockIdx.x * blockDim.x + threadIdx.x;
    size_t nth = (size_t)gridDim.x * blockDim.x;

    for (size_t i = tid; i < (size_t)BATCH * SEQ * KIN; i += nth) {
        int k = (int)(i % KIN);
        size_t bt = i / KIN;
        int b = (int)(bt / SEQ);
        g_xcat[i] = tf32_rna((k < 64) ? prim[bt * 64 + k] : aux[b * 32 + (k - 64)]);
    }
    for (size_t i = tid; i < (size_t)GATES * HID; i += nth) {
        int k  = (int)(i % HID);
        int cp = (int)(i / HID);
        int u = cp >> 2, gi = cp & 3;
        size_t r = (size_t)(gi * HID + u) * HID + k;
        g_Whh0h[i] = __float2half(Whh0[r]);
        g_Whh1h[i] = __float2half(Whh1[r]);
        g_Wih1h[i] = __float2half(Wih1[r]);
    }
    for (size_t i = tid; i < (size_t)GATES * KIN; i += nth) {
        int k  = (int)(i % KIN);
        int cp = (int)(i / KIN);
        int u = cp >> 2, gi = cp & 3;
        g_Wih0p[i] = tf32_rna(Wih0[(size_t)(gi * HID + u) * KIN + k]);
    }
    for (size_t i = tid; i < GATES; i += nth) {
        int u = (int)(i >> 2), gi = (int)(i & 3);
        int r = gi * HID + u;
        g_biasP[0][i] = bih0[r] + bhh0[r];
        g_biasP[1][i] = bih1[r] + bhh1[r];
    }
}

// ---------------- x_proj0 GEMM (tf32 wmma) ----------------
#define GT_M 128
#define GT_N 128
#define KCHUNK 16
#define SPAD 20

__global__ void __launch_bounds__(256) gemm_tf32()
{
    __shared__ float As[GT_M * SPAD];
    __shared__ float Bs[GT_N * SPAD];

    const float* A  = g_xcat;
    const float* Bm = g_Wih0p;
    const int K     = KIN;

    int tn = blockIdx.x;
    int tm = blockIdx.y;
    int tid = threadIdx.x;
    int wid = tid >> 5;
    int wm = wid >> 2, wn = wid & 3;

    wmma::fragment<wmma::accumulator, 16, 16, 8, float> acc[4][2];
#pragma unroll
    for (int i = 0; i < 4; i++)
#pragma unroll
        for (int j = 0; j < 2; j++) wmma::fill_fragment(acc[i][j], 0.0f);

    const float* Abase = A  + (size_t)tm * GT_M * K;
    const float* Bbase = Bm + (size_t)tn * GT_N * K;

    for (int k0 = 0; k0 < K; k0 += KCHUNK) {
        __syncthreads();
#pragma unroll
        for (int s = tid; s < GT_M * 4; s += 256) {
            int m = s >> 2, q = s & 3;
            *(float4*)&As[m * SPAD + q * 4] = *(const float4*)&Abase[(size_t)m * K + k0 + q * 4];
            *(float4*)&Bs[m * SPAD + q * 4] = *(const float4*)&Bbase[(size_t)m * K + k0 + q * 4];
        }
        __syncthreads();
#pragma unroll
        for (int ks = 0; ks < 2; ks++) {
            wmma::fragment<wmma::matrix_b, 16, 16, 8, wmma::precision::tf32, wmma::col_major> bf[2];
#pragma unroll
            for (int j = 0; j < 2; j++)
                wmma::load_matrix_sync(bf[j], &Bs[(wn * 32 + j * 16) * SPAD + ks * 8], SPAD);
#pragma unroll
            for (int i = 0; i < 4; i++) {
                wmma::fragment<wmma::matrix_a, 16, 16, 8, wmma::precision::tf32, wmma::row_major> af;
                wmma::load_matrix_sync(af, &As[(wm * 64 + i * 16) * SPAD + ks * 8], SPAD);
#pragma unroll
                for (int j = 0; j < 2; j++) wmma::mma_sync(acc[i][j], af, bf[j], acc[i][j]);
            }
        }
    }
#pragma unroll
    for (int i = 0; i < 4; i++)
#pragma unroll
        for (int j = 0; j < 2; j++) {
            int gm = tm * GT_M + wm * 64 + i * 16;
            int gn = tn * GT_N + wn * 32 + j * 16;
            wmma::store_matrix_sync(&g_xproj[(size_t)gm * GATES + gn], acc[i][j], GATES,
                                    wmma::mem_row_major);
        }
}

// ---------------- fused dual-layer persistent scan (fp16 operands, fp32 accum) ----------------
__global__ void __launch_bounds__(NT_SCAN) scan_fused()
{
    extern __shared__ char smem_raw[];

    const int tid  = threadIdx.x;
    const int w    = tid >> 5;
    const int lane = tid & 31;
    const int grp  = blockIdx.x >> 6;          // 0 = layer0, 1 = layer1
    const int c    = blockIdx.x & 63;          // gate-col block [32c, 32c+32)

    const __half hzero = __float2half(0.0f);
    for (int i = blockIdx.x * NT_SCAN + tid; i < BATCH * HID; i += NB_SCAN * NT_SCAN) {
        g_hbuf0[0][i] = hzero;
        g_hbuf1[0][i] = hzero;
    }

    unsigned round = ld_acquire_gpu(&g_flags[blockIdx.x][0]);

    if (grp == 0) {
        // ---------------- layer 0 ----------------
        __half* As = (__half*)smem_raw;             // [64][APADH]
        __half* Ws = As + 64 * APADH;               // [32][APADH]
        float*  sg = (float*)smem_raw;              // alias: [4][64][SGP]

        const int mh = w & 1;                       // m half (32 rows)
        const int kq = w >> 1;                      // k quarter (128 cols)

        {   // stage W slice once
            const __half* Wg = g_Whh0h + (size_t)c * CCOLS * HID;
#pragma unroll 4
            for (int idx = tid; idx < CCOLS * 64; idx += NT_SCAN) {
                int n = idx >> 6, q = idx & 63;
                *(float4*)(Ws + n * APADH + q * 8) = *(const float4*)(Wg + (size_t)n * HID + q * 8);
            }
        }

        const int b0 = tid >> 3,  ul0 = tid & 7,  gc0 = ul0 * 4;
        const int p1 = tid + NT_SCAN;
        const int b1 = p1 >> 3,   ul1 = p1 & 7,   gc1 = ul1 * 4;
        const float4 bias0 = *(const float4*)(g_biasP[0] + c * CCOLS + gc0);
        const float4 bias1 = *(const float4*)(g_biasP[0] + c * CCOLS + gc1);
        const float* xpp0 = g_xproj + (size_t)b0 * SEQ * GATES + c * CCOLS + gc0;
        const float* xpp1 = g_xproj + (size_t)b1 * SEQ * GATES + c * CCOLS + gc1;
        const int u0 = c * 8 + ul0, u1 = c * 8 + ul1;
        float cst0 = 0.0f, cst1 = 0.0f;

        grid_barrier_round(++round);

        float4 xp0 = __ldcs((const float4*)xpp0);
        float4 xp1 = __ldcs((const float4*)xpp1);

        for (int r = 0; r < SEQ + 1; r++) {
            if (r < SEQ) {
                const int t = r;
                const __half* hread  = g_hbuf0[t & 1];
                __half*       hwrite = g_hbuf0[(t & 1) ^ 1];

                {   // warp-local stage: rows mh*32..+32, cols kq*128..+128 (16 f4/lane)
                    const __half* src = hread + (size_t)(mh * 32) * HID + kq * 128;
                    __half* dst = As + (mh * 32) * APADH + kq * 128;
#pragma unroll
                    for (int i = 0; i < 16; i++) {
                        int idx = lane + 32 * i;
                        int row = idx >> 4, c8 = idx & 15;
                        *(float4*)(dst + row * APADH + c8 * 8) =
                            __ldcg((const float4*)(src + (size_t)row * HID + c8 * 8));
                    }
                }
                __syncwarp();

                wmma::fragment<wmma::accumulator, 16, 16, 16, float> acc[2][2];
#pragma unroll
                for (int i = 0; i < 2; i++)
#pragma unroll
                    for (int j = 0; j < 2; j++) wmma::fill_fragment(acc[i][j], 0.0f);

                const __half* Abase = As + (mh * 32) * APADH + kq * 128;
                const __half* Bbase = Ws + kq * 128;
#pragma unroll
                for (int ks = 0; ks < 8; ks++) {
                    wmma::fragment<wmma::matrix_a, 16, 16, 16, __half, wmma::row_major> af[2];
                    wmma::fragment<wmma::matrix_b, 16, 16, 16, __half, wmma::col_major> bf[2];
#pragma unroll
                    for (int i = 0; i < 2; i++)
                        wmma::load_matrix_sync(af[i], Abase + i * 16 * APADH + ks * 16, APADH);
#pragma unroll
                    for (int j = 0; j < 2; j++)
                        wmma::load_matrix_sync(bf[j], Bbase + j * 16 * APADH + ks * 16, APADH);
#pragma unroll
                    for (int i = 0; i < 2; i++)
#pragma unroll
                        for (int j = 0; j < 2; j++) wmma::mma_sync(acc[i][j], af[i], bf[j], acc[i][j]);
                }
                __syncthreads();
#pragma unroll
                for (int i = 0; i < 2; i++)
#pragma unroll
                    for (int j = 0; j < 2; j++)
                        wmma::store_matrix_sync(&sg[kq * (64 * SGP) + (mh * 32 + i * 16) * SGP + j * 16],
                                                acc[i][j], SGP, wmma::mem_row_major);
                __syncthreads();

                {
                    float4 s0 = *(const float4*)&sg[0 * (64 * SGP) + b0 * SGP + gc0];
                    float4 s1 = *(const float4*)&sg[1 * (64 * SGP) + b0 * SGP + gc0];
                    float4 s2 = *(const float4*)&sg[2 * (64 * SGP) + b0 * SGP + gc0];
                    float4 s3 = *(const float4*)&sg[3 * (64 * SGP) + b0 * SGP + gc0];
                    float pi = s0.x + s1.x + s2.x + s3.x + xp0.x + bias0.x;
                    float pf = s0.y + s1.y + s2.y + s3.y + xp0.y + bias0.y;
                    float pg = s0.z + s1.z + s2.z + s3.z + xp0.z + bias0.z;
                    float po = s0.w + s1.w + s2.w + s3.w + xp0.w + bias0.w;
                    float ig = sigm(pi), fg = sigm(pf), gg = tanhf(pg), og = sigm(po);
                    cst0 = fg * cst0 + ig * gg;
                    hwrite[b0 * HID + u0] = __float2half(og * tanhf(cst0));
                }
                {
                    float4 s0 = *(const float4*)&sg[0 * (64 * SGP) + b1 * SGP + gc1];
                    float4 s1 = *(const float4*)&sg[1 * (64 * SGP) + b1 * SGP + gc1];
                    float4 s2 = *(const float4*)&sg[2 * (64 * SGP) + b1 * SGP + gc1];
                    float4 s3 = *(const float4*)&sg[3 * (64 * SGP) + b1 * SGP + gc1];
                    float pi = s0.x + s1.x + s2.x + s3.x + xp1.x + bias1.x;
                    float pf = s0.y + s1.y + s2.y + s3.y + xp1.y + bias1.y;
                    float pg = s0.z + s1.z + s2.z + s3.z + xp1.z + bias1.z;
                    float po = s0.w + s1.w + s2.w + s3.w + xp1.w + bias1.w;
                    float ig = sigm(pi), fg = sigm(pf), gg = tanhf(pg), og = sigm(po);
                    cst1 = fg * cst1 + ig * gg;
                    hwrite[b1 * HID + u1] = __float2half(og * tanhf(cst1));
                }
                int tn2 = (t + 1 < SEQ) ? (t + 1) : (SEQ - 1);
                xp0 = __ldcs((const float4*)(xpp0 + (size_t)tn2 * GATES));
                xp1 = __ldcs((const float4*)(xpp1 + (size_t)tn2 * GATES));
            }
            grid_barrier_round(++round);
        }
    } else {
        // ---------------- layer 1 (lag 1, single-segment: full 64-row concat A) ----------------
        __half* Ws1 = (__half*)smem_raw;            // [32][W1PADH]: cols 0-511 Wih1, 512-1023 Whh1
        __half* As1 = Ws1 + 32 * W1PADH;            // [64][W1PADH]: concat [h0(t) | h1(t-1)]
        float*  sg  = (float*)As1;                  // alias: [4][64][SGP]

        const int mh = w & 1;                       // m half (32 rows)
        const int kq = w >> 1;                      // 256-col quarter of concat K=1024

        {   // stage concat W once: 32 rows x 1024 halfs
            const __half* Wx = g_Wih1h + (size_t)c * CCOLS * HID;
            const __half* Wh = g_Whh1h + (size_t)c * CCOLS * HID;
#pragma unroll 4
            for (int idx = tid; idx < CCOLS * 128; idx += NT_SCAN) {
                int n = idx >> 7, q = idx & 127;
                const __half* src = (q < 64) ? (Wx + (size_t)n * HID + q * 8)
                                             : (Wh + (size_t)n * HID + (q - 64) * 8);
                *(float4*)(Ws1 + n * W1PADH + q * 8) = *(const float4*)src;
            }
        }

        const int b0 = tid >> 3,  ul0 = tid & 7,  gc0 = ul0 * 4;
        const int p1 = tid + NT_SCAN;
        const int b1 = p1 >> 3,   ul1 = p1 & 7,   gc1 = ul1 * 4;
        const float4 bias0 = *(const float4*)(g_biasP[1] + c * CCOLS + gc0);
        const float4 bias1 = *(const float4*)(g_biasP[1] + c * CCOLS + gc1);
        const int u0 = c * 8 + ul0, u1 = c * 8 + ul1;
        float cst0 = 0.0f, cst1 = 0.0f;

        grid_barrier_round(++round);

        for (int r = 0; r < SEQ + 1; r++) {
            if (r >= 1) {
                const int t = r - 1;
                const __half* h0read = g_hbuf0[(t & 1) ^ 1];   // h0[t]
                const __half* h1read = g_hbuf1[t & 1];         // h1[t-1]
                __half*       hwrite = g_hbuf1[(t & 1) ^ 1];

                {   // warp-local stage: rows mh*32..+32, concat cols kq*256..+256 (32 f4/lane)
                    const __half* src = (kq < 2) ? h0read : h1read;
                    const int kc = (kq & 1) * 256;             // col offset within source
                    const __half* s = src + (size_t)(mh * 32) * HID + kc;
                    __half* dst = As1 + (mh * 32) * W1PADH + kq * 256;
#pragma unroll
                    for (int i = 0; i < 32; i++) {
                        int idx = lane + 32 * i;
                        int row = idx >> 5, c8 = idx & 31;
                        *(float4*)(dst + row * W1PADH + c8 * 8) =
                            __ldcg((const float4*)(s + (size_t)row * HID + c8 * 8));
                    }
                }
                __syncwarp();

                wmma::fragment<wmma::accumulator, 16, 16, 16, float> acc[2][2];
#pragma unroll
                for (int i = 0; i < 2; i++)
#pragma unroll
                    for (int j = 0; j < 2; j++) wmma::fill_fragment(acc[i][j], 0.0f);

                const __half* Abase = As1 + (mh * 32) * W1PADH + kq * 256;
                const __half* Bbase = Ws1 + kq * 256;
#pragma unroll
                for (int ks = 0; ks < 16; ks++) {
                    wmma::fragment<wmma::matrix_a, 16, 16, 16, __half, wmma::row_major> af[2];
                    wmma::fragment<wmma::matrix_b, 16, 16, 16, __half, wmma::col_major> bf[2];
#pragma unroll
                    for (int i = 0; i < 2; i++)
                        wmma::load_matrix_sync(af[i], Abase + i * 16 * W1PADH + ks * 16, W1PADH);
#pragma unroll
                    for (int j = 0; j < 2; j++)
                        wmma::load_matrix_sync(bf[j], Bbase + j * 16 * W1PADH + ks * 16, W1PADH);
#pragma unroll
                    for (int i = 0; i < 2; i++)
#pragma unroll
                        for (int j = 0; j < 2; j++) wmma::mma_sync(acc[i][j], af[i], bf[j], acc[i][j]);
                }
                __syncthreads();   // all warps done reading As1 before sg (alias) write
#pragma unroll
                for (int i = 0; i < 2; i++)
#pragma unroll
                    for (int j = 0; j < 2; j++)
                        wmma::store_matrix_sync(&sg[kq * (64 * SGP) + (mh * 32 + i * 16) * SGP + j * 16],
                                                acc[i][j], SGP, wmma::mem_row_major);
                __syncthreads();

                {
                    float4 s0 = *(const float4*)&sg[0 * (64 * SGP) + b0 * SGP + gc0];
                    float4 s1 = *(const float4*)&sg[1 * (64 * SGP) + b0 * SGP + gc0];
                    float4 s2 = *(const float4*)&sg[2 * (64 * SGP) + b0 * SGP + gc0];
                    float4 s3 = *(const float4*)&sg[3 * (64 * SGP) + b0 * SGP + gc0];
                    float pi = s0.x + s1.x + s2.x + s3.x + bias0.x;
                    float pf = s0.y + s1.y + s2.y + s3.y + bias0.y;
                    float pg = s0.z + s1.z + s2.z + s3.z + bias0.z;
                    float po = s0.w + s1.w + s2.w + s3.w + bias0.w;
                    float ig = sigm(pi), fg = sigm(pf), gg = tanhf(pg), og = sigm(po);
                    cst0 = fg * cst0 + ig * gg;
                    hwrite[b0 * HID + u0] = __float2half(og * tanhf(cst0));
                }
                {
                    float4 s0 = *(const float4*)&sg[0 * (64 * SGP) + b1 * SGP + gc1];
                    float4 s1 = *(const float4*)&sg[1 * (64 * SGP) + b1 * SGP + gc1];
                    float4 s2 = *(const float4*)&sg[2 * (64 * SGP) + b1 * SGP + gc1];
                    float4 s3 = *(const float4*)&sg[3 * (64 * SGP) + b1 * SGP + gc1];
                    float pi = s0.x + s1.x + s2.x + s3.x + bias1.x;
                    float pf = s0.y + s1.y + s2.y + s3.y + bias1.y;
                    float pg = s0.z + s1.z + s2.z + s3.z + bias1.z;
                    float po = s0.w + s1.w + s2.w + s3.w + bias1.w;
                    float ig = sigm(pi), fg = sigm(pf), gg = tanhf(pg), og = sigm(po);
                    cst1 = fg * cst1 + ig * gg;
                    hwrite[b1 * HID + u1] = __float2half(og * tanhf(cst1));
                }
            }
            grid_barrier_round(++round);
        }
    }
}

// ---------------- output projection (split-K x2 + smem reduce, half h) ----------------
__global__ void out_kernel(const float* __restrict__ Wout, const float* __restrict__ bout,
                           float* __restrict__ out)
{
    __shared__ float red[256];
    int b = blockIdx.x;
    int t = threadIdx.x;          // 256
    int o = t & 127, half = t >> 7;
    const __half2* h2 = (const __half2*)(g_hbuf1[0] + b * HID) + half * 128;
    const float2*  w2 = (const float2*)(Wout + (size_t)o * HID) + half * 128;
    float acc = 0.0f;
#pragma unroll 16
    for (int i = 0; i < 128; i++) {
        float2 hh = __half22float2(h2[i]);
        float2 ww = w2[i];
        acc += hh.x * ww.x + hh.y * ww.y;
    }
    red[t] = acc;
    __syncthreads();
    if (t < 128) out[b * ODIM + t] = red[t] + red[t + 128] + bout[t];
}

// ---------------- launch ----------------
extern "C" void kernel_launch(void* const* d_in, const int* in_sizes, int n_in,
                              void* d_out, int out_size)
{
    (void)in_sizes; (void)n_in; (void)out_size;
    const float* prim = (const float*)d_in[0];
    const float* aux  = (const float*)d_in[1];
    const float* Wih0 = (const float*)d_in[2];
    const float* Whh0 = (const float*)d_in[3];
    const float* bih0 = (const float*)d_in[4];
    const float* bhh0 = (const float*)d_in[5];
    const float* Wih1 = (const float*)d_in[6];
    const float* Whh1 = (const float*)d_in[7];
    const float* bih1 = (const float*)d_in[8];
    const float* bhh1 = (const float*)d_in[9];
    const float* Wout = (const float*)d_in[10];
    const float* bout = (const float*)d_in[11];
    float* out = (float*)d_out;

    static bool attr_set = false;
    if (!attr_set) {
        cudaFuncSetAttribute(scan_fused, cudaFuncAttributeMaxDynamicSharedMemorySize,
                             SCAN_SMEM_BYTES);
        attr_set = true;
    }

    prep_kernel<<<1024, 256>>>(prim, aux, Wih0, Whh0, bih0, bhh0, Wih1, Whh1, bih1, bhh1);
    gemm_tf32<<<dim3(16, 256), 256>>>();                      // x_proj0
    scan_fused<<<NB_SCAN, NT_SCAN, SCAN_SMEM_BYTES>>>();      // both layers, pipelined
    out_kernel<<<BATCH, 256>>>(Wout, bout, out);
}

// round 14
// speedup vs baseline: 1.0013x; 1.0013x over previous
#include <cuda_runtime.h>
#include <cuda_bf16.h>
#include <cuda_fp16.h>
#include <mma.h>

using namespace nvcuda;

#define BATCH 64
#define SEQ   512
#define HID   512
#define GATES 2048
#define KIN   96
#define ODIM  128

#define NB_SCAN 128     // 64 layer-0 CTAs + 64 layer-1 CTAs
#define NT_SCAN 256
#define CCOLS   32
#define APADH   520     // 512+8 halfs: row stride 1040B ≡ 16B mod 128B
#define W1PADH  1032    // 1024+8 halfs: 2064B ≡ 16B mod 128B
#define SGP     36
// layer-0: As half[64][APADH] + Ws half[32][APADH]; sg(float) aliases As
#define L0_TOTAL_B   ((64 + 32) * APADH * 2)           // 99,840
// layer-1: Ws1 half[32][W1PADH] + As1 half[64][W1PADH]; sg(float) aliases As1
#define L1_TOTAL_B   ((32 + 64) * W1PADH * 2)          // 198,144
#define SCAN_SMEM_BYTES L1_TOTAL_B                     // 198,144 B (< 227 KB)

// ---------------- static device scratch ----------------
__device__ float  g_xproj[(size_t)BATCH * SEQ * GATES];
__device__ float  g_xcat[(size_t)BATCH * SEQ * KIN];
__device__ float  g_Wih0p[GATES * KIN];
__device__ __half g_Whh0h[GATES * HID];
__device__ __half g_Wih1h[GATES * HID];
__device__ __half g_Whh1h[GATES * HID];
__device__ float  g_biasP[2][GATES];
__device__ __half g_hbuf0[2][BATCH * HID];
__device__ __half g_hbuf1[2][BATCH * HID];
__device__ unsigned g_flags[NB_SCAN][32];   // per-CTA round flags, 128B apart

// ---------------- sync primitives ----------------
__device__ __forceinline__ unsigned ld_acquire_gpu(const unsigned* p) {
    unsigned v;
    asm volatile("ld.acquire.gpu.global.u32 %0, [%1];" : "=r"(v) : "l"(p) : "memory");
    return v;
}
__device__ __forceinline__ void st_release_gpu(unsigned* p, unsigned v) {
    asm volatile("st.release.gpu.global.u32 [%0], %1;" :: "l"(p), "r"(v) : "memory");
}

// all-to-all flag barrier: arrival = 1 release store to own flag; wait = warp 0
// polls all 128 flags in parallel. Monotonic rounds, replay-safe.
__device__ __forceinline__ void grid_barrier_round(unsigned round) {
    __syncthreads();
    if (threadIdx.x < 32) {
        if (threadIdx.x == 0)
            st_release_gpu(&g_flags[blockIdx.x][0], round);
        const int lane = threadIdx.x;
        bool ok;
        do {
            ok = true;
#pragma unroll
            for (int i = 0; i < NB_SCAN / 32; i++) {
                unsigned f = ld_acquire_gpu(&g_flags[lane + 32 * i][0]);
                ok &= ((int)(f - round) >= 0);
            }
        } while (!__all_sync(0xffffffffu, ok));
    }
    __syncthreads();
}

__device__ __forceinline__ float sigm(float x) { return 1.0f / (1.0f + expf(-x)); }

__device__ __forceinline__ float tf32_rna(float x) {
    unsigned u;
    asm("cvt.rna.tf32.f32 %0, %1;" : "=r"(u) : "f"(x));
    return __uint_as_float(u);
}

// ---------------- prep ----------------
__global__ void prep_kernel(const float* __restrict__ prim, const float* __restrict__ aux,
                            const float* __restrict__ Wih0, const float* __restrict__ Whh0,
                            const float* __restrict__ bih0, const float* __restrict__ bhh0,
                            const float* __restrict__ Wih1, const float* __restrict__ Whh1,
                            const float* __restrict__ bih1, const float* __restrict__ bhh1)
{
    size_t tid = (size_t)blockIdx.x * blockDim.x + threadIdx.x;
    size_t nth = (size_t)gridDim.x * blockDim.x;

    for (size_t i = tid; i < (size_t)BATCH * SEQ * KIN; i += nth) {
        int k = (int)(i % KIN);
        size_t bt = i / KIN;
        int b = (int)(bt / SEQ);
        g_xcat[i] = tf32_rna((k < 64) ? prim[bt * 64 + k] : aux[b * 32 + (k - 64)]);
    }
    for (size_t i = tid; i < (size_t)GATES * HID; i += nth) {
        int k  = (int)(i % HID);
        int cp = (int)(i / HID);
        int u = cp >> 2, gi = cp & 3;
        size_t r = (size_t)(gi * HID + u) * HID + k;
        g_Whh0h[i] = __float2half(Whh0[r]);
        g_Whh1h[i] = __float2half(Whh1[r]);
        g_Wih1h[i] = __float2half(Wih1[r]);
    }
    for (size_t i = tid; i < (size_t)GATES * KIN; i += nth) {
        int k  = (int)(i % KIN);
        int cp = (int)(i / KIN);
        int u = cp >> 2, gi = cp & 3;
        g_Wih0p[i] = tf32_rna(Wih0[(size_t)(gi * HID + u) * KIN + k]);
    }
    for (size_t i = tid; i < GATES; i += nth) {
        int u = (int)(i >> 2), gi = (int)(i & 3);
        int r = gi * HID + u;
        g_biasP[0][i] = bih0[r] + bhh0[r];
        g_biasP[1][i] = bih1[r] + bhh1[r];
    }
}

// ---------------- x_proj0 GEMM (tf32 wmma) ----------------
#define GT_M 128
#define GT_N 128
#define KCHUNK 16
#define SPAD 20

__global__ void __launch_bounds__(256) gemm_tf32()
{
    __shared__ float As[GT_M * SPAD];
    __shared__ float Bs[GT_N * SPAD];

    const float* A  = g_xcat;
    const float* Bm = g_Wih0p;
    const int K     = KIN;

    int tn = blockIdx.x;
    int tm = blockIdx.y;
    int tid = threadIdx.x;
    int wid = tid >> 5;
    int wm = wid >> 2, wn = wid & 3;

    wmma::fragment<wmma::accumulator, 16, 16, 8, float> acc[4][2];
#pragma unroll
    for (int i = 0; i < 4; i++)
#pragma unroll
        for (int j = 0; j < 2; j++) wmma::fill_fragment(acc[i][j], 0.0f);

    const float* Abase = A  + (size_t)tm * GT_M * K;
    const float* Bbase = Bm + (size_t)tn * GT_N * K;

    for (int k0 = 0; k0 < K; k0 += KCHUNK) {
        __syncthreads();
#pragma unroll
        for (int s = tid; s < GT_M * 4; s += 256) {
            int m = s >> 2, q = s & 3;
            *(float4*)&As[m * SPAD + q * 4] = *(const float4*)&Abase[(size_t)m * K + k0 + q * 4];
            *(float4*)&Bs[m * SPAD + q * 4] = *(const float4*)&Bbase[(size_t)m * K + k0 + q * 4];
        }
        __syncthreads();
#pragma unroll
        for (int ks = 0; ks < 2; ks++) {
            wmma::fragment<wmma::matrix_b, 16, 16, 8, wmma::precision::tf32, wmma::col_major> bf[2];
#pragma unroll
            for (int j = 0; j < 2; j++)
                wmma::load_matrix_sync(bf[j], &Bs[(wn * 32 + j * 16) * SPAD + ks * 8], SPAD);
#pragma unroll
            for (int i = 0; i < 4; i++) {
                wmma::fragment<wmma::matrix_a, 16, 16, 8, wmma::precision::tf32, wmma::row_major> af;
                wmma::load_matrix_sync(af, &As[(wm * 64 + i * 16) * SPAD + ks * 8], SPAD);
#pragma unroll
                for (int j = 0; j < 2; j++) wmma::mma_sync(acc[i][j], af, bf[j], acc[i][j]);
            }
        }
    }
#pragma unroll
    for (int i = 0; i < 4; i++)
#pragma unroll
        for (int j = 0; j < 2; j++) {
            int gm = tm * GT_M + wm * 64 + i * 16;
            int gn = tn * GT_N + wn * 32 + j * 16;
            wmma::store_matrix_sync(&g_xproj[(size_t)gm * GATES + gn], acc[i][j], GATES,
                                    wmma::mem_row_major);
        }
}

// ---------------- fused dual-layer persistent scan (fp16 operands, fp32 accum) ----------------
__global__ void __launch_bounds__(NT_SCAN) scan_fused()
{
    extern __shared__ char smem_raw[];

    const int tid  = threadIdx.x;
    const int w    = tid >> 5;
    const int lane = tid & 31;
    const int grp  = blockIdx.x >> 6;          // 0 = layer0, 1 = layer1
    const int c    = blockIdx.x & 63;          // gate-col block [32c, 32c+32)

    const __half hzero = __float2half(0.0f);
    for (int i = blockIdx.x * NT_SCAN + tid; i < BATCH * HID; i += NB_SCAN * NT_SCAN) {
        g_hbuf0[0][i] = hzero;
        g_hbuf1[0][i] = hzero;
    }

    unsigned round = ld_acquire_gpu(&g_flags[blockIdx.x][0]);

    if (grp == 0) {
        // ---------------- layer 0 ----------------
        __half* As = (__half*)smem_raw;             // [64][APADH]
        __half* Ws = As + 64 * APADH;               // [32][APADH]
        float*  sg = (float*)smem_raw;              // alias: [4][64][SGP]

        const int mh = w & 1;                       // m half (32 rows)
        const int kq = w >> 1;                      // k quarter (128 cols)

        {   // stage W slice once
            const __half* Wg = g_Whh0h + (size_t)c * CCOLS * HID;
#pragma unroll 4
            for (int idx = tid; idx < CCOLS * 64; idx += NT_SCAN) {
                int n = idx >> 6, q = idx & 63;
                *(float4*)(Ws + n * APADH + q * 8) = *(const float4*)(Wg + (size_t)n * HID + q * 8);
            }
        }

        const int b0 = tid >> 3,  ul0 = tid & 7,  gc0 = ul0 * 4;
        const int p1 = tid + NT_SCAN;
        const int b1 = p1 >> 3,   ul1 = p1 & 7,   gc1 = ul1 * 4;
        const float4 bias0 = *(const float4*)(g_biasP[0] + c * CCOLS + gc0);
        const float4 bias1 = *(const float4*)(g_biasP[0] + c * CCOLS + gc1);
        const float* xpp0 = g_xproj + (size_t)b0 * SEQ * GATES + c * CCOLS + gc0;
        const float* xpp1 = g_xproj + (size_t)b1 * SEQ * GATES + c * CCOLS + gc1;
        const int u0 = c * 8 + ul0, u1 = c * 8 + ul1;
        float cst0 = 0.0f, cst1 = 0.0f;

        grid_barrier_round(++round);

        float4 xp0 = __ldcs((const float4*)xpp0);
        float4 xp1 = __ldcs((const float4*)xpp1);

        for (int r = 0; r < SEQ + 1; r++) {
            if (r < SEQ) {
                const int t = r;
                const __half* hread  = g_hbuf0[t & 1];
                __half*       hwrite = g_hbuf0[(t & 1) ^ 1];

                {   // warp-local stage: rows mh*32..+32, cols kq*128..+128 (16 f4/lane)
                    const __half* src = hread + (size_t)(mh * 32) * HID + kq * 128;
                    __half* dst = As + (mh * 32) * APADH + kq * 128;
#pragma unroll
                    for (int i = 0; i < 16; i++) {
                        int idx = lane + 32 * i;
                        int row = idx >> 4, c8 = idx & 15;
                        *(float4*)(dst + row * APADH + c8 * 8) =
                            __ldcg((const float4*)(src + (size_t)row * HID + c8 * 8));
                    }
                }
                __syncwarp();

                wmma::fragment<wmma::accumulator, 16, 16, 16, float> acc[2][2];
#pragma unroll
                for (int i = 0; i < 2; i++)
#pragma unroll
                    for (int j = 0; j < 2; j++) wmma::fill_fragment(acc[i][j], 0.0f);

                const __half* Abase = As + (mh * 32) * APADH + kq * 128;
                const __half* Bbase = Ws + kq * 128;
#pragma unroll
                for (int ks = 0; ks < 8; ks++) {
                    wmma::fragment<wmma::matrix_a, 16, 16, 16, __half, wmma::row_major> af[2];
                    wmma::fragment<wmma::matrix_b, 16, 16, 16, __half, wmma::col_major> bf[2];
#pragma unroll
                    for (int i = 0; i < 2; i++)
                        wmma::load_matrix_sync(af[i], Abase + i * 16 * APADH + ks * 16, APADH);
#pragma unroll
                    for (int j = 0; j < 2; j++)
                        wmma::load_matrix_sync(bf[j], Bbase + j * 16 * APADH + ks * 16, APADH);
#pragma unroll
                    for (int i = 0; i < 2; i++)
#pragma unroll
                        for (int j = 0; j < 2; j++) wmma::mma_sync(acc[i][j], af[i], bf[j], acc[i][j]);
                }
                __syncthreads();
#pragma unroll
                for (int i = 0; i < 2; i++)
#pragma unroll
                    for (int j = 0; j < 2; j++)
                        wmma::store_matrix_sync(&sg[kq * (64 * SGP) + (mh * 32 + i * 16) * SGP + j * 16],
                                                acc[i][j], SGP, wmma::mem_row_major);
                __syncthreads();

                {
                    float4 s0 = *(const float4*)&sg[0 * (64 * SGP) + b0 * SGP + gc0];
                    float4 s1 = *(const float4*)&sg[1 * (64 * SGP) + b0 * SGP + gc0];
                    float4 s2 = *(const float4*)&sg[2 * (64 * SGP) + b0 * SGP + gc0];
                    float4 s3 = *(const float4*)&sg[3 * (64 * SGP) + b0 * SGP + gc0];
                    float pi = s0.x + s1.x + s2.x + s3.x + xp0.x + bias0.x;
                    float pf = s0.y + s1.y + s2.y + s3.y + xp0.y + bias0.y;
                    float pg = s0.z + s1.z + s2.z + s3.z + xp0.z + bias0.z;
                    float po = s0.w + s1.w + s2.w + s3.w + xp0.w + bias0.w;
                    float ig = sigm(pi), fg = sigm(pf), gg = tanhf(pg), og = sigm(po);
                    cst0 = fg * cst0 + ig * gg;
                    hwrite[b0 * HID + u0] = __float2half(og * tanhf(cst0));
                }
                {
                    float4 s0 = *(const float4*)&sg[0 * (64 * SGP) + b1 * SGP + gc1];
                    float4 s1 = *(const float4*)&sg[1 * (64 * SGP) + b1 * SGP + gc1];
                    float4 s2 = *(const float4*)&sg[2 * (64 * SGP) + b1 * SGP + gc1];
                    float4 s3 = *(const float4*)&sg[3 * (64 * SGP) + b1 * SGP + gc1];
                    float pi = s0.x + s1.x + s2.x + s3.x + xp1.x + bias1.x;
                    float pf = s0.y + s1.y + s2.y + s3.y + xp1.y + bias1.y;
                    float pg = s0.z + s1.z + s2.z + s3.z + xp1.z + bias1.z;
                    float po = s0.w + s1.w + s2.w + s3.w + xp1.w + bias1.w;
                    float ig = sigm(pi), fg = sigm(pf), gg = tanhf(pg), og = sigm(po);
                    cst1 = fg * cst1 + ig * gg;
                    hwrite[b1 * HID + u1] = __float2half(og * tanhf(cst1));
                }
                int tn2 = (t + 1 < SEQ) ? (t + 1) : (SEQ - 1);
                xp0 = __ldcs((const float4*)(xpp0 + (size_t)tn2 * GATES));
                xp1 = __ldcs((const float4*)(xpp1 + (size_t)tn2 * GATES));
            }
            grid_barrier_round(++round);
        }
    } else {
        // ---------------- layer 1 (lag 1, single-segment: full 64-row concat A) ----------------
        __half* Ws1 = (__half*)smem_raw;            // [32][W1PADH]: cols 0-511 Wih1, 512-1023 Whh1
        __half* As1 = Ws1 + 32 * W1PADH;            // [64][W1PADH]: concat [h0(t) | h1(t-1)]
        float*  sg  = (float*)As1;                  // alias: [4][64][SGP]

        const int mh = w & 1;                       // m half (32 rows)
        const int kq = w >> 1;                      // 256-col quarter of concat K=1024

        {   // stage concat W once: 32 rows x 1024 halfs
            const __half* Wx = g_Wih1h + (size_t)c * CCOLS * HID;
            const __half* Wh = g_Whh1h + (size_t)c * CCOLS * HID;
#pragma unroll 4
            for (int idx = tid; idx < CCOLS * 128; idx += NT_SCAN) {
                int n = idx >> 7, q = idx & 127;
                const __half* src = (q < 64) ? (Wx + (size_t)n * HID + q * 8)
                                             : (Wh + (size_t)n * HID + (q - 64) * 8);
                *(float4*)(Ws1 + n * W1PADH + q * 8) = *(const float4*)src;
            }
        }

        const int b0 = tid >> 3,  ul0 = tid & 7,  gc0 = ul0 * 4;
        const int p1 = tid + NT_SCAN;
        const int b1 = p1 >> 3,   ul1 = p1 & 7,   gc1 = ul1 * 4;
        const float4 bias0 = *(const float4*)(g_biasP[1] + c * CCOLS + gc0);
        const float4 bias1 = *(const float4*)(g_biasP[1] + c * CCOLS + gc1);
        const int u0 = c * 8 + ul0, u1 = c * 8 + ul1;
        float cst0 = 0.0f, cst1 = 0.0f;

        grid_barrier_round(++round);

        for (int r = 0; r < SEQ + 1; r++) {
            if (r >= 1) {
                const int t = r - 1;
                const __half* h0read = g_hbuf0[(t & 1) ^ 1];   // h0[t]
                const __half* h1read = g_hbuf1[t & 1];         // h1[t-1]
                __half*       hwrite = g_hbuf1[(t & 1) ^ 1];

                {   // warp-local stage: rows mh*32..+32, concat cols kq*256..+256 (32 f4/lane)
                    const __half* src = (kq < 2) ? h0read : h1read;
                    const int kc = (kq & 1) * 256;             // col offset within source
                    const __half* s = src + (size_t)(mh * 32) * HID + kc;
                    __half* dst = As1 + (mh * 32) * W1PADH + kq * 256;
#pragma unroll
                    for (int i = 0; i < 32; i++) {
                        int idx = lane + 32 * i;
                        int row = idx >> 5, c8 = idx & 31;
                        *(float4*)(dst + row * W1PADH + c8 * 8) =
                            __ldcg((const float4*)(s + (size_t)row * HID + c8 * 8));
                    }
                }
                __syncwarp();

                wmma::fragment<wmma::accumulator, 16, 16, 16, float> acc[2][2];
#pragma unroll
                for (int i = 0; i < 2; i++)
#pragma unroll
                    for (int j = 0; j < 2; j++) wmma::fill_fragment(acc[i][j], 0.0f);

                const __half* Abase = As1 + (mh * 32) * W1PADH + kq * 256;
                const __half* Bbase = Ws1 + kq * 256;
#pragma unroll
                for (int ks = 0; ks < 16; ks++) {
                    wmma::fragment<wmma::matrix_a, 16, 16, 16, __half, wmma::row_major> af[2];
                    wmma::fragment<wmma::matrix_b, 16, 16, 16, __half, wmma::col_major> bf[2];
#pragma unroll
                    for (int i = 0; i < 2; i++)
                        wmma::load_matrix_sync(af[i], Abase + i * 16 * W1PADH + ks * 16, W1PADH);
#pragma unroll
                    for (int j = 0; j < 2; j++)
                        wmma::load_matrix_sync(bf[j], Bbase + j * 16 * W1PADH + ks * 16, W1PADH);
#pragma unroll
                    for (int i = 0; i < 2; i++)
#pragma unroll
                        for (int j = 0; j < 2; j++) wmma::mma_sync(acc[i][j], af[i], bf[j], acc[i][j]);
                }
                __syncthreads();   // all warps done reading As1 before sg (alias) write
#pragma unroll
                for (int i = 0; i < 2; i++)
#pragma unroll
                    for (int j = 0; j < 2; j++)
                        wmma::store_matrix_sync(&sg[kq * (64 * SGP) + (mh * 32 + i * 16) * SGP + j * 16],
                                                acc[i][j], SGP, wmma::mem_row_major);
                __syncthreads();

                {
                    float4 s0 = *(const float4*)&sg[0 * (64 * SGP) + b0 * SGP + gc0];
                    float4 s1 = *(const float4*)&sg[1 * (64 * SGP) + b0 * SGP + gc0];
                    float4 s2 = *(const float4*)&sg[2 * (64 * SGP) + b0 * SGP + gc0];
                    float4 s3 = *(const float4*)&sg[3 * (64 * SGP) + b0 * SGP + gc0];
                    float pi = s0.x + s1.x + s2.x + s3.x + bias0.x;
                    float pf = s0.y + s1.y + s2.y + s3.y + bias0.y;
                    float pg = s0.z + s1.z + s2.z + s3.z + bias0.z;
                    float po = s0.w + s1.w + s2.w + s3.w + bias0.w;
                    float ig = sigm(pi), fg = sigm(pf), gg = tanhf(pg), og = sigm(po);
                    cst0 = fg * cst0 + ig * gg;
                    hwrite[b0 * HID + u0] = __float2half(og * tanhf(cst0));
                }
                {
                    float4 s0 = *(const float4*)&sg[0 * (64 * SGP) + b1 * SGP + gc1];
                    float4 s1 = *(const float4*)&sg[1 * (64 * SGP) + b1 * SGP + gc1];
                    float4 s2 = *(const float4*)&sg[2 * (64 * SGP) + b1 * SGP + gc1];
                    float4 s3 = *(const float4*)&sg[3 * (64 * SGP) + b1 * SGP + gc1];
                    float pi = s0.x + s1.x + s2.x + s3.x + bias1.x;
                    float pf = s0.y + s1.y + s2.y + s3.y + bias1.y;
                    float pg = s0.z + s1.z + s2.z + s3.z + bias1.z;
                    float po = s0.w + s1.w + s2.w + s3.w + bias1.w;
                    float ig = sigm(pi), fg = sigm(pf), gg = tanhf(pg), og = sigm(po);
                    cst1 = fg * cst1 + ig * gg;
                    hwrite[b1 * HID + u1] = __float2half(og * tanhf(cst1));
                }
            }
            grid_barrier_round(++round);
        }
    }
}

// ---------------- output projection (split-K x2 + smem reduce, half h) ----------------
__global__ void out_kernel(const float* __restrict__ Wout, const float* __restrict__ bout,
                           float* __restrict__ out)
{
    __shared__ float red[256];
    int b = blockIdx.x;
    int t = threadIdx.x;          // 256
    int o = t & 127, half = t >> 7;
    const __half2* h2 = (const __half2*)(g_hbuf1[0] + b * HID) + half * 128;
    const float2*  w2 = (const float2*)(Wout + (size_t)o * HID) + half * 128;
    float acc = 0.0f;
#pragma unroll 16
    for (int i = 0; i < 128; i++) {
        float2 hh = __half22float2(h2[i]);
        float2 ww = w2[i];
        acc += hh.x * ww.x + hh.y * ww.y;
    }
    red[t] = acc;
    __syncthreads();
    if (t < 128) out[b * ODIM + t] = red[t] + red[t + 128] + bout[t];
}

// ---------------- launch ----------------
extern "C" void kernel_launch(void* const* d_in, const int* in_sizes, int n_in,
                              void* d_out, int out_size)
{
    (void)in_sizes; (void)n_in; (void)out_size;
    const float* prim = (const float*)d_in[0];
    const float* aux  = (const float*)d_in[1];
    const float* Wih0 = (const float*)d_in[2];
    const float* Whh0 = (const float*)d_in[3];
    const float* bih0 = (const float*)d_in[4];
    const float* bhh0 = (const float*)d_in[5];
    const float* Wih1 = (const float*)d_in[6];
    const float* Whh1 = (const float*)d_in[7];
    const float* bih1 = (const float*)d_in[8];
    const float* bhh1 = (const float*)d_in[9];
    const float* Wout = (const float*)d_in[10];
    const float* bout = (const float*)d_in[11];
    float* out = (float*)d_out;

    static bool attr_set = false;
    if (!attr_set) {
        cudaFuncSetAttribute(scan_fused, cudaFuncAttributeMaxDynamicSharedMemorySize,
                             SCAN_SMEM_BYTES);
        attr_set = true;
    }

    prep_kernel<<<1024, 256>>>(prim, aux, Wih0, Whh0, bih0, bhh0, Wih1, Whh1, bih1, bhh1);
    gemm_tf32<<<dim3(16, 256), 256>>>();                      // x_proj0
    scan_fused<<<NB_SCAN, NT_SCAN, SCAN_SMEM_BYTES>>>();      // both layers, pipelined
    out_kernel<<<BATCH, 256>>>(Wout, bout, out);
}

// round 15
// speedup vs baseline: 1.0886x; 1.0871x over previous
#include <cuda_runtime.h>
#include <cuda_bf16.h>
#include <cuda_fp16.h>
#include <mma.h>

using namespace nvcuda;

#define BATCH 64
#define SEQ   512
#define HID   512
#define GATES 2048
#define KIN   96
#define ODIM  128

#define NB_SCAN 128     // 64 layer-0 CTAs + 64 layer-1 CTAs
#define NT_SCAN 256
#define APADH   520     // 512+8 halfs
#define W1PADH  1032    // 1024+8 halfs
#define SGP0    64      // L0 sg stride (floats) — fits inside As alias region
#define SGP1    68      // L1 sg stride (floats)
// layer-0: As half[32][APADH] + Ws half[64][APADH]; sg(float)[4][32][SGP0] aliases As
#define L0_TOTAL_B   ((32 + 64) * APADH * 2)           // 99,840
// layer-1: Ws1 half[64][W1PADH] + As1 half[32][W1PADH]; sg(float)[4][32][SGP1] aliases As1
#define L1_TOTAL_B   ((64 + 32) * W1PADH * 2)          // 198,144
#define SCAN_SMEM_BYTES L1_TOTAL_B                     // 198,144 B (< 227 KB)

// ---------------- static device scratch ----------------
__device__ float  g_xproj[(size_t)BATCH * SEQ * GATES];
__device__ float  g_xcat[(size_t)BATCH * SEQ * KIN];
__device__ float  g_Wih0p[GATES * KIN];
__device__ __half g_Whh0h[GATES * HID];
__device__ __half g_Wih1h[GATES * HID];
__device__ __half g_Whh1h[GATES * HID];
__device__ float  g_biasP[2][GATES];
__device__ __half g_hbuf0[2][BATCH * HID];
__device__ __half g_hbuf1[2][BATCH * HID];
__device__ unsigned g_flags[NB_SCAN][32];   // per-CTA round flags, 128B apart

// ---------------- sync primitives ----------------
__device__ __forceinline__ unsigned ld_acquire_gpu(const unsigned* p) {
    unsigned v;
    asm volatile("ld.acquire.gpu.global.u32 %0, [%1];" : "=r"(v) : "l"(p) : "memory");
    return v;
}
__device__ __forceinline__ void st_release_gpu(unsigned* p, unsigned v) {
    asm volatile("st.release.gpu.global.u32 [%0], %1;" :: "l"(p), "r"(v) : "memory");
}

// all-to-all flag barrier: arrival = 1 release store to own flag; wait = warp 0
// polls all 128 flags in parallel. Monotonic rounds, replay-safe.
__device__ __forceinline__ void grid_barrier_round(unsigned round) {
    __syncthreads();
    if (threadIdx.x < 32) {
        if (threadIdx.x == 0)
            st_release_gpu(&g_flags[blockIdx.x][0], round);
        const int lane = threadIdx.x;
        bool ok;
        do {
            ok = true;
#pragma unroll
            for (int i = 0; i < NB_SCAN / 32; i++) {
                unsigned f = ld_acquire_gpu(&g_flags[lane + 32 * i][0]);
                ok &= ((int)(f - round) >= 0);
            }
        } while (!__all_sync(0xffffffffu, ok));
    }
    __syncthreads();
}

__device__ __forceinline__ float sigm(float x) { return 1.0f / (1.0f + expf(-x)); }

__device__ __forceinline__ float tf32_rna(float x) {
    unsigned u;
    asm("cvt.rna.tf32.f32 %0, %1;" : "=r"(u) : "f"(x));
    return __uint_as_float(u);
}

// ---------------- prep ----------------
__global__ void prep_kernel(const float* __restrict__ prim, const float* __restrict__ aux,
                            const float* __restrict__ Wih0, const float* __restrict__ Whh0,
                            const float* __restrict__ bih0, const float* __restrict__ bhh0,
                            const float* __restrict__ Wih1, const float* __restrict__ Whh1,
                            const float* __restrict__ bih1, const float* __restrict__ bhh1)
{
    size_t tid = (size_t)blockIdx.x * blockDim.x + threadIdx.x;
    size_t nth = (size_t)gridDim.x * blockDim.x;

    for (size_t i = tid; i < (size_t)BATCH * SEQ * KIN; i += nth) {
        int k = (int)(i % KIN);
        size_t bt = i / KIN;
        int b = (int)(bt / SEQ);
        g_xcat[i] = tf32_rna((k < 64) ? prim[bt * 64 + k] : aux[b * 32 + (k - 64)]);
    }
    for (size_t i = tid; i < (size_t)GATES * HID; i += nth) {
        int k  = (int)(i % HID);
        int cp = (int)(i / HID);
        int u = cp >> 2, gi = cp & 3;
        size_t r = (size_t)(gi * HID + u) * HID + k;
        g_Whh0h[i] = __float2half(Whh0[r]);
        g_Whh1h[i] = __float2half(Whh1[r]);
        g_Wih1h[i] = __float2half(Wih1[r]);
    }
    for (size_t i = tid; i < (size_t)GATES * KIN; i += nth) {
        int k  = (int)(i % KIN);
        int cp = (int)(i / KIN);
        int u = cp >> 2, gi = cp & 3;
        g_Wih0p[i] = tf32_rna(Wih0[(size_t)(gi * HID + u) * KIN + k]);
    }
    for (size_t i = tid; i < GATES; i += nth) {
        int u = (int)(i >> 2), gi = (int)(i & 3);
        int r = gi * HID + u;
        g_biasP[0][i] = bih0[r] + bhh0[r];
        g_biasP[1][i] = bih1[r] + bhh1[r];
    }
}

// ---------------- x_proj0 GEMM (tf32 wmma) ----------------
#define GT_M 128
#define GT_N 128
#define KCHUNK 16
#define SPAD 20

__global__ void __launch_bounds__(256) gemm_tf32()
{
    __shared__ float As[GT_M * SPAD];
    __shared__ float Bs[GT_N * SPAD];

    const float* A  = g_xcat;
    const float* Bm = g_Wih0p;
    const int K     = KIN;

    int tn = blockIdx.x;
    int tm = blockIdx.y;
    int tid = threadIdx.x;
    int wid = tid >> 5;
    int wm = wid >> 2, wn = wid & 3;

    wmma::fragment<wmma::accumulator, 16, 16, 8, float> acc[4][2];
#pragma unroll
    for (int i = 0; i < 4; i++)
#pragma unroll
        for (int j = 0; j < 2; j++) wmma::fill_fragment(acc[i][j], 0.0f);

    const float* Abase = A  + (size_t)tm * GT_M * K;
    const float* Bbase = Bm + (size_t)tn * GT_N * K;

    for (int k0 = 0; k0 < K; k0 += KCHUNK) {
        __syncthreads();
#pragma unroll
        for (int s = tid; s < GT_M * 4; s += 256) {
            int m = s >> 2, q = s & 3;
            *(float4*)&As[m * SPAD + q * 4] = *(const float4*)&Abase[(size_t)m * K + k0 + q * 4];
            *(float4*)&Bs[m * SPAD + q * 4] = *(const float4*)&Bbase[(size_t)m * K + k0 + q * 4];
        }
        __syncthreads();
#pragma unroll
        for (int ks = 0; ks < 2; ks++) {
            wmma::fragment<wmma::matrix_b, 16, 16, 8, wmma::precision::tf32, wmma::col_major> bf[2];
#pragma unroll
            for (int j = 0; j < 2; j++)
                wmma::load_matrix_sync(bf[j], &Bs[(wn * 32 + j * 16) * SPAD + ks * 8], SPAD);
#pragma unroll
            for (int i = 0; i < 4; i++) {
                wmma::fragment<wmma::matrix_a, 16, 16, 8, wmma::precision::tf32, wmma::row_major> af;
                wmma::load_matrix_sync(af, &As[(wm * 64 + i * 16) * SPAD + ks * 8], SPAD);
#pragma unroll
                for (int j = 0; j < 2; j++) wmma::mma_sync(acc[i][j], af, bf[j], acc[i][j]);
            }
        }
    }
#pragma unroll
    for (int i = 0; i < 4; i++)
#pragma unroll
        for (int j = 0; j < 2; j++) {
            int gm = tm * GT_M + wm * 64 + i * 16;
            int gn = tn * GT_N + wn * 32 + j * 16;
            wmma::store_matrix_sync(&g_xproj[(size_t)gm * GATES + gn], acc[i][j], GATES,
                                    wmma::mem_row_major);
        }
}

// ---------------- fused dual-layer persistent scan ----------------
// Each group's 64 CTAs = 32 gate-groups (64 gate cols = 16 units) x 2 batch-groups (32 rows).
// Halves per-CTA A staging vs gate-only split; per-CTA mma work unchanged.
__global__ void __launch_bounds__(NT_SCAN) scan_fused()
{
    extern __shared__ char smem_raw[];

    const int tid  = threadIdx.x;
    const int w    = tid >> 5;
    const int lane = tid & 31;
    const int grp  = blockIdx.x >> 6;          // 0 = layer0, 1 = layer1
    const int c    = blockIdx.x & 63;
    const int bg   = c & 1;                    // batch group: rows [bg*32, +32)
    const int cg   = c >> 1;                   // gate group: cols [cg*64, +64), units [cg*16,+16)

    const int mh = w & 1;                      // 16-row half of the 32-row batch slice
    const int kq = w >> 1;                     // k quarter

    const __half hzero = __float2half(0.0f);
    for (int i = blockIdx.x * NT_SCAN + tid; i < BATCH * HID; i += NB_SCAN * NT_SCAN) {
        g_hbuf0[0][i] = hzero;
        g_hbuf1[0][i] = hzero;
    }

    unsigned round = ld_acquire_gpu(&g_flags[blockIdx.x][0]);

    // elementwise mapping (both layers): 2 outputs/thread over 32 b x 16 units
    const int p0 = tid,            b0l = p0 >> 4, ul0 = p0 & 15, gc0 = ul0 * 4;
    const int p1 = tid + NT_SCAN,  b1l = p1 >> 4, ul1 = p1 & 15, gc1 = ul1 * 4;
    const int gb0 = bg * 32 + b0l, gb1 = bg * 32 + b1l;
    const int u0 = cg * 16 + ul0,  u1 = cg * 16 + ul1;

    if (grp == 0) {
        // ---------------- layer 0 ----------------
        __half* As = (__half*)smem_raw;             // [32][APADH]
        __half* Ws = As + 32 * APADH;               // [64][APADH]
        float*  sg = (float*)smem_raw;              // alias: [4][32][SGP0] (32,768B <= 33,280B)

        {   // stage W slice once: 64 gate rows x 512
            const __half* Wg = g_Whh0h + (size_t)cg * 64 * HID;
#pragma unroll 4
            for (int idx = tid; idx < 64 * 64; idx += NT_SCAN) {
                int n = idx >> 6, q = idx & 63;
                *(float4*)(Ws + n * APADH + q * 8) = *(const float4*)(Wg + (size_t)n * HID + q * 8);
            }
        }

        const float4 bias0 = *(const float4*)(g_biasP[0] + cg * 64 + gc0);
        const float4 bias1 = *(const float4*)(g_biasP[0] + cg * 64 + gc1);
        const float* xpp0 = g_xproj + (size_t)gb0 * SEQ * GATES + cg * 64 + gc0;
        const float* xpp1 = g_xproj + (size_t)gb1 * SEQ * GATES + cg * 64 + gc1;
        float cst0 = 0.0f, cst1 = 0.0f;

        grid_barrier_round(++round);

        float4 xp0 = __ldcs((const float4*)xpp0);
        float4 xp1 = __ldcs((const float4*)xpp1);

        for (int r = 0; r < SEQ + 1; r++) {
            if (r < SEQ) {
                const int t = r;
                const __half* hread  = g_hbuf0[t & 1];
                __half*       hwrite = g_hbuf0[(t & 1) ^ 1];

                {   // warp-local stage: rows bg*32+mh*16..+16, cols kq*128..+128 (8 f4/lane)
                    const __half* src = hread + (size_t)(bg * 32 + mh * 16) * HID + kq * 128;
                    __half* dst = As + (mh * 16) * APADH + kq * 128;
#pragma unroll
                    for (int i = 0; i < 8; i++) {
                        int idx = lane + 32 * i;
                        int row = idx >> 4, c8 = idx & 15;
                        *(float4*)(dst + row * APADH + c8 * 8) =
                            __ldcg((const float4*)(src + (size_t)row * HID + c8 * 8));
                    }
                }
                __syncwarp();

                // warp tile: 16(m) x 64(n), K=128
                wmma::fragment<wmma::accumulator, 16, 16, 16, float> acc[4];
#pragma unroll
                for (int j = 0; j < 4; j++) wmma::fill_fragment(acc[j], 0.0f);

                const __half* Abase = As + (mh * 16) * APADH + kq * 128;
                const __half* Bbase = Ws + kq * 128;
#pragma unroll
                for (int ks = 0; ks < 8; ks++) {
                    wmma::fragment<wmma::matrix_a, 16, 16, 16, __half, wmma::row_major> af;
                    wmma::fragment<wmma::matrix_b, 16, 16, 16, __half, wmma::col_major> bf[4];
                    wmma::load_matrix_sync(af, Abase + ks * 16, APADH);
#pragma unroll
                    for (int j = 0; j < 4; j++)
                        wmma::load_matrix_sync(bf[j], Bbase + j * 16 * APADH + ks * 16, APADH);
#pragma unroll
                    for (int j = 0; j < 4; j++) wmma::mma_sync(acc[j], af, bf[j], acc[j]);
                }
                __syncthreads();   // all warps done reading As before sg (alias) write
#pragma unroll
                for (int j = 0; j < 4; j++)
                    wmma::store_matrix_sync(&sg[kq * (32 * SGP0) + (mh * 16) * SGP0 + j * 16],
                                            acc[j], SGP0, wmma::mem_row_major);
                __syncthreads();

                {
                    float4 s0 = *(const float4*)&sg[0 * (32 * SGP0) + b0l * SGP0 + gc0];
                    float4 s1 = *(const float4*)&sg[1 * (32 * SGP0) + b0l * SGP0 + gc0];
                    float4 s2 = *(const float4*)&sg[2 * (32 * SGP0) + b0l * SGP0 + gc0];
                    float4 s3 = *(const float4*)&sg[3 * (32 * SGP0) + b0l * SGP0 + gc0];
                    float pi = s0.x + s1.x + s2.x + s3.x + xp0.x + bias0.x;
                    float pf = s0.y + s1.y + s2.y + s3.y + xp0.y + bias0.y;
                    float pg = s0.z + s1.z + s2.z + s3.z + xp0.z + bias0.z;
                    float po = s0.w + s1.w + s2.w + s3.w + xp0.w + bias0.w;
                    float ig = sigm(pi), fg = sigm(pf), gg = tanhf(pg), og = sigm(po);
                    cst0 = fg * cst0 + ig * gg;
                    hwrite[gb0 * HID + u0] = __float2half(og * tanhf(cst0));
                }
                {
                    float4 s0 = *(const float4*)&sg[0 * (32 * SGP0) + b1l * SGP0 + gc1];
                    float4 s1 = *(const float4*)&sg[1 * (32 * SGP0) + b1l * SGP0 + gc1];
                    float4 s2 = *(const float4*)&sg[2 * (32 * SGP0) + b1l * SGP0 + gc1];
                    float4 s3 = *(const float4*)&sg[3 * (32 * SGP0) + b1l * SGP0 + gc1];
                    float pi = s0.x + s1.x + s2.x + s3.x + xp1.x + bias1.x;
                    float pf = s0.y + s1.y + s2.y + s3.y + xp1.y + bias1.y;
                    float pg = s0.z + s1.z + s2.z + s3.z + xp1.z + bias1.z;
                    float po = s0.w + s1.w + s2.w + s3.w + xp1.w + bias1.w;
                    float ig = sigm(pi), fg = sigm(pf), gg = tanhf(pg), og = sigm(po);
                    cst1 = fg * cst1 + ig * gg;
                    hwrite[gb1 * HID + u1] = __float2half(og * tanhf(cst1));
                }
                int tn2 = (t + 1 < SEQ) ? (t + 1) : (SEQ - 1);
                xp0 = __ldcs((const float4*)(xpp0 + (size_t)tn2 * GATES));
                xp1 = __ldcs((const float4*)(xpp1 + (size_t)tn2 * GATES));
            }
            grid_barrier_round(++round);
        }
    } else {
        // ---------------- layer 1 (lag 1) ----------------
        __half* Ws1 = (__half*)smem_raw;            // [64][W1PADH]: cols 0-511 Wih1, 512-1023 Whh1
        __half* As1 = Ws1 + 64 * W1PADH;            // [32][W1PADH]: concat [h0(t) | h1(t-1)] rows bg*32..
        float*  sg  = (float*)As1;                  // alias: [4][32][SGP1] (34,816B <= 66,048B)

        {   // stage concat W once: 64 gate rows x 1024
            const __half* Wx = g_Wih1h + (size_t)cg * 64 * HID;
            const __half* Wh = g_Whh1h + (size_t)cg * 64 * HID;
#pragma unroll 4
            for (int idx = tid; idx < 64 * 128; idx += NT_SCAN) {
                int n = idx >> 7, q = idx & 127;
                const __half* src = (q < 64) ? (Wx + (size_t)n * HID + q * 8)
                                             : (Wh + (size_t)n * HID + (q - 64) * 8);
                *(float4*)(Ws1 + n * W1PADH + q * 8) = *(const float4*)src;
            }
        }

        const float4 bias0 = *(const float4*)(g_biasP[1] + cg * 64 + gc0);
        const float4 bias1 = *(const float4*)(g_biasP[1] + cg * 64 + gc1);
        float cst0 = 0.0f, cst1 = 0.0f;

        grid_barrier_round(++round);

        for (int r = 0; r < SEQ + 1; r++) {
            if (r >= 1) {
                const int t = r - 1;
                const __half* h0read = g_hbuf0[(t & 1) ^ 1];   // h0[t]
                const __half* h1read = g_hbuf1[t & 1];         // h1[t-1]
                __half*       hwrite = g_hbuf1[(t & 1) ^ 1];

                {   // warp-local stage: rows bg*32+mh*16..+16, concat cols kq*256..+256 (16 f4/lane)
                    const __half* src = (kq < 2) ? h0read : h1read;
                    const int kc = (kq & 1) * 256;
                    const __half* s = src + (size_t)(bg * 32 + mh * 16) * HID + kc;
                    __half* dst = As1 + (mh * 16) * W1PADH + kq * 256;
#pragma unroll
                    for (int i = 0; i < 16; i++) {
                        int idx = lane + 32 * i;
                        int row = idx >> 5, c8 = idx & 31;
                        *(float4*)(dst + row * W1PADH + c8 * 8) =
                            __ldcg((const float4*)(s + (size_t)row * HID + c8 * 8));
                    }
                }
                __syncwarp();

                // warp tile: 16(m) x 64(n), K=256
                wmma::fragment<wmma::accumulator, 16, 16, 16, float> acc[4];
#pragma unroll
                for (int j = 0; j < 4; j++) wmma::fill_fragment(acc[j], 0.0f);

                const __half* Abase = As1 + (mh * 16) * W1PADH + kq * 256;
                const __half* Bbase = Ws1 + kq * 256;
#pragma unroll
                for (int ks = 0; ks < 16; ks++) {
                    wmma::fragment<wmma::matrix_a, 16, 16, 16, __half, wmma::row_major> af;
                    wmma::fragment<wmma::matrix_b, 16, 16, 16, __half, wmma::col_major> bf[4];
                    wmma::load_matrix_sync(af, Abase + ks * 16, W1PADH);
#pragma unroll
                    for (int j = 0; j < 4; j++)
                        wmma::load_matrix_sync(bf[j], Bbase + j * 16 * W1PADH + ks * 16, W1PADH);
#pragma unroll
                    for (int j = 0; j < 4; j++) wmma::mma_sync(acc[j], af, bf[j], acc[j]);
                }
                __syncthreads();   // all warps done reading As1 before sg (alias) write
#pragma unroll
                for (int j = 0; j < 4; j++)
                    wmma::store_matrix_sync(&sg[kq * (32 * SGP1) + (mh * 16) * SGP1 + j * 16],
                                            acc[j], SGP1, wmma::mem_row_major);
                __syncthreads();

                {
                    float4 s0 = *(const float4*)&sg[0 * (32 * SGP1) + b0l * SGP1 + gc0];
                    float4 s1 = *(const float4*)&sg[1 * (32 * SGP1) + b0l * SGP1 + gc0];
                    float4 s2 = *(const float4*)&sg[2 * (32 * SGP1) + b0l * SGP1 + gc0];
                    float4 s3 = *(const float4*)&sg[3 * (32 * SGP1) + b0l * SGP1 + gc0];
                    float pi = s0.x + s1.x + s2.x + s3.x + bias0.x;
                    float pf = s0.y + s1.y + s2.y + s3.y + bias0.y;
                    float pg = s0.z + s1.z + s2.z + s3.z + bias0.z;
                    float po = s0.w + s1.w + s2.w + s3.w + bias0.w;
                    float ig = sigm(pi), fg = sigm(pf), gg = tanhf(pg), og = sigm(po);
                    cst0 = fg * cst0 + ig * gg;
                    hwrite[gb0 * HID + u0] = __float2half(og * tanhf(cst0));
                }
                {
                    float4 s0 = *(const float4*)&sg[0 * (32 * SGP1) + b1l * SGP1 + gc1];
                    float4 s1 = *(const float4*)&sg[1 * (32 * SGP1) + b1l * SGP1 + gc1];
                    float4 s2 = *(const float4*)&sg[2 * (32 * SGP1) + b1l * SGP1 + gc1];
                    float4 s3 = *(const float4*)&sg[3 * (32 * SGP1) + b1l * SGP1 + gc1];
                    float pi = s0.x + s1.x + s2.x + s3.x + bias1.x;
                    float pf = s0.y + s1.y + s2.y + s3.y + bias1.y;
                    float pg = s0.z + s1.z + s2.z + s3.z + bias1.z;
                    float po = s0.w + s1.w + s2.w + s3.w + bias1.w;
                    float ig = sigm(pi), fg = sigm(pf), gg = tanhf(pg), og = sigm(po);
                    cst1 = fg * cst1 + ig * gg;
                    hwrite[gb1 * HID + u1] = __float2half(og * tanhf(cst1));
                }
            }
            grid_barrier_round(++round);
        }
    }
}

// ---------------- output projection (split-K x2 + smem reduce, half h) ----------------
__global__ void out_kernel(const float* __restrict__ Wout, const float* __restrict__ bout,
                           float* __restrict__ out)
{
    __shared__ float red[256];
    int b = blockIdx.x;
    int t = threadIdx.x;          // 256
    int o = t & 127, half = t >> 7;
    const __half2* h2 = (const __half2*)(g_hbuf1[0] + b * HID) + half * 128;
    const float2*  w2 = (const float2*)(Wout + (size_t)o * HID) + half * 128;
    float acc = 0.0f;
#pragma unroll 16
    for (int i = 0; i < 128; i++) {
        float2 hh = __half22float2(h2[i]);
        float2 ww = w2[i];
        acc += hh.x * ww.x + hh.y * ww.y;
    }
    red[t] = acc;
    __syncthreads();
    if (t < 128) out[b * ODIM + t] = red[t] + red[t + 128] + bout[t];
}

// ---------------- launch ----------------
extern "C" void kernel_launch(void* const* d_in, const int* in_sizes, int n_in,
                              void* d_out, int out_size)
{
    (void)in_sizes; (void)n_in; (void)out_size;
    const float* prim = (const float*)d_in[0];
    const float* aux  = (const float*)d_in[1];
    const float* Wih0 = (const float*)d_in[2];
    const float* Whh0 = (const float*)d_in[3];
    const float* bih0 = (const float*)d_in[4];
    const float* bhh0 = (const float*)d_in[5];
    const float* Wih1 = (const float*)d_in[6];
    const float* Whh1 = (const float*)d_in[7];
    const float* bih1 = (const float*)d_in[8];
    const float* bhh1 = (const float*)d_in[9];
    const float* Wout = (const float*)d_in[10];
    const float* bout = (const float*)d_in[11];
    float* out = (float*)d_out;

    static bool attr_set = false;
    if (!attr_set) {
        cudaFuncSetAttribute(scan_fused, cudaFuncAttributeMaxDynamicSharedMemorySize,
                             SCAN_SMEM_BYTES);
        attr_set = true;
    }

    prep_kernel<<<1024, 256>>>(prim, aux, Wih0, Whh0, bih0, bhh0, Wih1, Whh1, bih1, bhh1);
    gemm_tf32<<<dim3(16, 256), 256>>>();                      // x_proj0
    scan_fused<<<NB_SCAN, NT_SCAN, SCAN_SMEM_BYTES>>>();      // both layers, pipelined
    out_kernel<<<BATCH, 256>>>(Wout, bout, out);
}

// round 16
// speedup vs baseline: 1.0987x; 1.0093x over previous
#include <cuda_runtime.h>
#include <cuda_bf16.h>
#include <cuda_fp16.h>
#include <mma.h>

using namespace nvcuda;

#define BATCH 64
#define SEQ   512
#define HID   512
#define GATES 2048
#define KIN   96
#define ODIM  128

#define NB_SCAN 128     // 64 layer-0 CTAs + 64 layer-1 CTAs
#define NT_SCAN 256
#define APADH   520     // 512+8 halfs
#define W1PADH  1032    // 1024+8 halfs
#define SGP0    64      // L0 sg stride (floats)
#define SGP1    68      // L1 sg stride (floats)
#define L0_TOTAL_B   ((32 + 64) * APADH * 2)           // 99,840
#define L1_TOTAL_B   ((64 + 32) * W1PADH * 2)          // 198,144
#define SCAN_SMEM_BYTES L1_TOTAL_B                     // 198,144 B (< 227 KB)

// ---------------- static device scratch ----------------
__device__ float  g_xproj[(size_t)BATCH * SEQ * GATES];
__device__ float  g_xcat[(size_t)BATCH * SEQ * KIN];
__device__ float  g_Wih0p[GATES * KIN];
__device__ __half g_Whh0h[GATES * HID];
__device__ __half g_Wih1h[GATES * HID];
__device__ __half g_Whh1h[GATES * HID];
__device__ float  g_biasP[2][GATES];
__device__ __half g_h0ring[4][BATCH * HID];  // h0[t] in ring[t&3]; ring[3] = h0[-1] = zeros
__device__ __half g_hbuf1[2][BATCH * HID];
__device__ unsigned g_flags[NB_SCAN][32];    // per-CTA round flags, 128B apart

// ---------------- sync primitives ----------------
__device__ __forceinline__ unsigned ld_acquire_gpu(const unsigned* p) {
    unsigned v;
    asm volatile("ld.acquire.gpu.global.u32 %0, [%1];" : "=r"(v) : "l"(p) : "memory");
    return v;
}
__device__ __forceinline__ void st_release_gpu(unsigned* p, unsigned v) {
    asm volatile("st.release.gpu.global.u32 [%0], %1;" :: "l"(p), "r"(v) : "memory");
}

// all-to-all flag barrier with group lag.
// lag_l1: this CTA only requires L1-group flags >= round - lag_l1 (L0 uses 2; L1 uses 0).
// Monotone thresholds -> deadlock-free; monotonic rounds -> graph-replay safe.
__device__ __forceinline__ void grid_barrier_round(unsigned round, unsigned lag_l1) {
    __syncthreads();
    if (threadIdx.x < 32) {
        if (threadIdx.x == 0)
            st_release_gpu(&g_flags[blockIdx.x][0], round);
        const int lane = threadIdx.x;
        bool ok;
        do {
            ok = true;
#pragma unroll
            for (int i = 0; i < NB_SCAN / 32; i++) {
                int cta = lane + 32 * i;
                unsigned tgt = round - ((cta >> 6) ? lag_l1 : 0u);
                unsigned f = ld_acquire_gpu(&g_flags[cta][0]);
                ok &= ((int)(f - tgt) >= 0);
            }
        } while (!__all_sync(0xffffffffu, ok));
    }
    __syncthreads();
}

__device__ __forceinline__ float sigm(float x) { return 1.0f / (1.0f + expf(-x)); }

__device__ __forceinline__ float tf32_rna(float x) {
    unsigned u;
    asm("cvt.rna.tf32.f32 %0, %1;" : "=r"(u) : "f"(x));
    return __uint_as_float(u);
}

// ---------------- prep ----------------
__global__ void prep_kernel(const float* __restrict__ prim, const float* __restrict__ aux,
                            const float* __restrict__ Wih0, const float* __restrict__ Whh0,
                            const float* __restrict__ bih0, const float* __restrict__ bhh0,
                            const float* __restrict__ Wih1, const float* __restrict__ Whh1,
                            const float* __restrict__ bih1, const float* __restrict__ bhh1)
{
    size_t tid = (size_t)blockIdx.x * blockDim.x + threadIdx.x;
    size_t nth = (size_t)gridDim.x * blockDim.x;

    for (size_t i = tid; i < (size_t)BATCH * SEQ * KIN; i += nth) {
        int k = (int)(i % KIN);
        size_t bt = i / KIN;
        int b = (int)(bt / SEQ);
        g_xcat[i] = tf32_rna((k < 64) ? prim[bt * 64 + k] : aux[b * 32 + (k - 64)]);
    }
    for (size_t i = tid; i < (size_t)GATES * HID; i += nth) {
        int k  = (int)(i % HID);
        int cp = (int)(i / HID);
        int u = cp >> 2, gi = cp & 3;
        size_t r = (size_t)(gi * HID + u) * HID + k;
        g_Whh0h[i] = __float2half(Whh0[r]);
        g_Whh1h[i] = __float2half(Whh1[r]);
        g_Wih1h[i] = __float2half(Wih1[r]);
    }
    for (size_t i = tid; i < (size_t)GATES * KIN; i += nth) {
        int k  = (int)(i % KIN);
        int cp = (int)(i / KIN);
        int u = cp >> 2, gi = cp & 3;
        g_Wih0p[i] = tf32_rna(Wih0[(size_t)(gi * HID + u) * KIN + k]);
    }
    for (size_t i = tid; i < GATES; i += nth) {
        int u = (int)(i >> 2), gi = (int)(i & 3);
        int r = gi * HID + u;
        g_biasP[0][i] = bih0[r] + bhh0[r];
        g_biasP[1][i] = bih1[r] + bhh1[r];
    }
}

// ---------------- x_proj0 GEMM (tf32 wmma) ----------------
#define GT_M 128
#define GT_N 128
#define KCHUNK 16
#define SPAD 20

__global__ void __launch_bounds__(256) gemm_tf32()
{
    __shared__ float As[GT_M * SPAD];
    __shared__ float Bs[GT_N * SPAD];

    const float* A  = g_xcat;
    const float* Bm = g_Wih0p;
    const int K     = KIN;

    int tn = blockIdx.x;
    int tm = blockIdx.y;
    int tid = threadIdx.x;
    int wid = tid >> 5;
    int wm = wid >> 2, wn = wid & 3;

    wmma::fragment<wmma::accumulator, 16, 16, 8, float> acc[4][2];
#pragma unroll
    for (int i = 0; i < 4; i++)
#pragma unroll
        for (int j = 0; j < 2; j++) wmma::fill_fragment(acc[i][j], 0.0f);

    const float* Abase = A  + (size_t)tm * GT_M * K;
    const float* Bbase = Bm + (size_t)tn * GT_N * K;

    for (int k0 = 0; k0 < K; k0 += KCHUNK) {
        __syncthreads();
#pragma unroll
        for (int s = tid; s < GT_M * 4; s += 256) {
            int m = s >> 2, q = s & 3;
            *(float4*)&As[m * SPAD + q * 4] = *(const float4*)&Abase[(size_t)m * K + k0 + q * 4];
            *(float4*)&Bs[m * SPAD + q * 4] = *(const float4*)&Bbase[(size_t)m * K + k0 + q * 4];
        }
        __syncthreads();
#pragma unroll
        for (int ks = 0; ks < 2; ks++) {
            wmma::fragment<wmma::matrix_b, 16, 16, 8, wmma::precision::tf32, wmma::col_major> bf[2];
#pragma unroll
            for (int j = 0; j < 2; j++)
                wmma::load_matrix_sync(bf[j], &Bs[(wn * 32 + j * 16) * SPAD + ks * 8], SPAD);
#pragma unroll
            for (int i = 0; i < 4; i++) {
                wmma::fragment<wmma::matrix_a, 16, 16, 8, wmma::precision::tf32, wmma::row_major> af;
                wmma::load_matrix_sync(af, &As[(wm * 64 + i * 16) * SPAD + ks * 8], SPAD);
#pragma unroll
                for (int j = 0; j < 2; j++) wmma::mma_sync(acc[i][j], af, bf[j], acc[i][j]);
            }
        }
    }
#pragma unroll
    for (int i = 0; i < 4; i++)
#pragma unroll
        for (int j = 0; j < 2; j++) {
            int gm = tm * GT_M + wm * 64 + i * 16;
            int gn = tn * GT_N + wn * 32 + j * 16;
            wmma::store_matrix_sync(&g_xproj[(size_t)gm * GATES + gn], acc[i][j], GATES,
                                    wmma::mem_row_major);
        }
}

// ---------------- fused dual-layer persistent scan (lag-2 decoupled) ----------------
// 64 CTAs/group = 32 gate-groups (64 cols) x 2 batch-groups (32 rows).
__global__ void __launch_bounds__(NT_SCAN) scan_fused()
{
    extern __shared__ char smem_raw[];

    const int tid  = threadIdx.x;
    const int w    = tid >> 5;
    const int lane = tid & 31;
    const int grp  = blockIdx.x >> 6;          // 0 = layer0, 1 = layer1
    const int c    = blockIdx.x & 63;
    const int bg   = c & 1;                    // batch group: rows [bg*32, +32)
    const int cg   = c >> 1;                   // gate group: cols [cg*64, +64)

    const int mh = w & 1;                      // 16-row half of the 32-row batch slice
    const int kq = w >> 1;                     // k quarter

    const __half hzero = __float2half(0.0f);
    // group-local zero-init: L0 group zeros ring[3] (h0[-1]); L1 group zeros h1buf[0].
    // Each consumer's barrier wait covers its producer group.
    if (grp == 0) {
        for (int i = c * NT_SCAN + tid; i < BATCH * HID; i += 64 * NT_SCAN)
            g_h0ring[3][i] = hzero;
    } else {
        for (int i = c * NT_SCAN + tid; i < BATCH * HID; i += 64 * NT_SCAN)
            g_hbuf1[0][i] = hzero;
    }

    unsigned round = ld_acquire_gpu(&g_flags[blockIdx.x][0]);

    // elementwise mapping: 2 outputs/thread over 32 b x 16 units
    const int p0 = tid,            b0l = p0 >> 4, ul0 = p0 & 15, gc0 = ul0 * 4;
    const int p1 = tid + NT_SCAN,  b1l = p1 >> 4, ul1 = p1 & 15, gc1 = ul1 * 4;
    const int gb0 = bg * 32 + b0l, gb1 = bg * 32 + b1l;
    const int u0 = cg * 16 + ul0,  u1 = cg * 16 + ul1;

    if (grp == 0) {
        // ---------------- layer 0 (runs up to 2 rounds ahead) ----------------
        __half* As = (__half*)smem_raw;             // [32][APADH]
        __half* Ws = As + 32 * APADH;               // [64][APADH]
        float*  sg = (float*)smem_raw;              // alias: [4][32][SGP0]

        {   // stage W slice once: 64 gate rows x 512
            const __half* Wg = g_Whh0h + (size_t)cg * 64 * HID;
#pragma unroll 4
            for (int idx = tid; idx < 64 * 64; idx += NT_SCAN) {
                int n = idx >> 6, q = idx & 63;
                *(float4*)(Ws + n * APADH + q * 8) = *(const float4*)(Wg + (size_t)n * HID + q * 8);
            }
        }

        const float4 bias0 = *(const float4*)(g_biasP[0] + cg * 64 + gc0);
        const float4 bias1 = *(const float4*)(g_biasP[0] + cg * 64 + gc1);
        const float* xpp0 = g_xproj + (size_t)gb0 * SEQ * GATES + cg * 64 + gc0;
        const float* xpp1 = g_xproj + (size_t)gb1 * SEQ * GATES + cg * 64 + gc1;
        float cst0 = 0.0f, cst1 = 0.0f;

        grid_barrier_round(++round, 2);

        float4 xp0 = __ldcs((const float4*)xpp0);
        float4 xp1 = __ldcs((const float4*)xpp1);

        for (int r = 0; r < SEQ + 1; r++) {
            if (r < SEQ) {
                const int t = r;
                const __half* hread  = g_h0ring[(t + 3) & 3];   // h0[t-1]
                __half*       hwrite = g_h0ring[t & 3];         // h0[t] (overwrites h0[t-4])

                {   // warp-local stage: rows bg*32+mh*16..+16, cols kq*128..+128 (8 f4/lane)
                    const __half* src = hread + (size_t)(bg * 32 + mh * 16) * HID + kq * 128;
                    __half* dst = As + (mh * 16) * APADH + kq * 128;
#pragma unroll
                    for (int i = 0; i < 8; i++) {
                        int idx = lane + 32 * i;
                        int row = idx >> 4, c8 = idx & 15;
                        *(float4*)(dst + row * APADH + c8 * 8) =
                            __ldcg((const float4*)(src + (size_t)row * HID + c8 * 8));
                    }
                }
                __syncwarp();

                // warp tile: 16(m) x 64(n), K=128
                wmma::fragment<wmma::accumulator, 16, 16, 16, float> acc[4];
#pragma unroll
                for (int j = 0; j < 4; j++) wmma::fill_fragment(acc[j], 0.0f);

                const __half* Abase = As + (mh * 16) * APADH + kq * 128;
                const __half* Bbase = Ws + kq * 128;
#pragma unroll
                for (int ks = 0; ks < 8; ks++) {
                    wmma::fragment<wmma::matrix_a, 16, 16, 16, __half, wmma::row_major> af;
                    wmma::fragment<wmma::matrix_b, 16, 16, 16, __half, wmma::col_major> bf[4];
                    wmma::load_matrix_sync(af, Abase + ks * 16, APADH);
#pragma unroll
                    for (int j = 0; j < 4; j++)
                        wmma::load_matrix_sync(bf[j], Bbase + j * 16 * APADH + ks * 16, APADH);
#pragma unroll
                    for (int j = 0; j < 4; j++) wmma::mma_sync(acc[j], af, bf[j], acc[j]);
                }
                __syncthreads();   // all warps done reading As before sg (alias) write
#pragma unroll
                for (int j = 0; j < 4; j++)
                    wmma::store_matrix_sync(&sg[kq * (32 * SGP0) + (mh * 16) * SGP0 + j * 16],
                                            acc[j], SGP0, wmma::mem_row_major);
                __syncthreads();

                {
                    float4 s0 = *(const float4*)&sg[0 * (32 * SGP0) + b0l * SGP0 + gc0];
                    float4 s1 = *(const float4*)&sg[1 * (32 * SGP0) + b0l * SGP0 + gc0];
                    float4 s2 = *(const float4*)&sg[2 * (32 * SGP0) + b0l * SGP0 + gc0];
                    float4 s3 = *(const float4*)&sg[3 * (32 * SGP0) + b0l * SGP0 + gc0];
                    float pi = s0.x + s1.x + s2.x + s3.x + xp0.x + bias0.x;
                    float pf = s0.y + s1.y + s2.y + s3.y + xp0.y + bias0.y;
                    float pg = s0.z + s1.z + s2.z + s3.z + xp0.z + bias0.z;
                    float po = s0.w + s1.w + s2.w + s3.w + xp0.w + bias0.w;
                    float ig = sigm(pi), fg = sigm(pf), gg = tanhf(pg), og = sigm(po);
                    cst0 = fg * cst0 + ig * gg;
                    hwrite[gb0 * HID + u0] = __float2half(og * tanhf(cst0));
                }
                {
                    float4 s0 = *(const float4*)&sg[0 * (32 * SGP0) + b1l * SGP0 + gc1];
                    float4 s1 = *(const float4*)&sg[1 * (32 * SGP0) + b1l * SGP0 + gc1];
                    float4 s2 = *(const float4*)&sg[2 * (32 * SGP0) + b1l * SGP0 + gc1];
                    float4 s3 = *(const float4*)&sg[3 * (32 * SGP0) + b1l * SGP0 + gc1];
                    float pi = s0.x + s1.x + s2.x + s3.x + xp1.x + bias1.x;
                    float pf = s0.y + s1.y + s2.y + s3.y + xp1.y + bias1.y;
                    float pg = s0.z + s1.z + s2.z + s3.z + xp1.z + bias1.z;
                    float po = s0.w + s1.w + s2.w + s3.w + xp1.w + bias1.w;
                    float ig = sigm(pi), fg = sigm(pf), gg = tanhf(pg), og = sigm(po);
                    cst1 = fg * cst1 + ig * gg;
                    hwrite[gb1 * HID + u1] = __float2half(og * tanhf(cst1));
                }
                int tn2 = (t + 1 < SEQ) ? (t + 1) : (SEQ - 1);
                xp0 = __ldcs((const float4*)(xpp0 + (size_t)tn2 * GATES));
                xp1 = __ldcs((const float4*)(xpp1 + (size_t)tn2 * GATES));
            }
            grid_barrier_round(++round, 2);
        }
    } else {
        // ---------------- layer 1 (lag 1 behind L0) ----------------
        __half* Ws1 = (__half*)smem_raw;            // [64][W1PADH]
        __half* As1 = Ws1 + 64 * W1PADH;            // [32][W1PADH]
        float*  sg  = (float*)As1;                  // alias: [4][32][SGP1]

        {   // stage concat W once: 64 gate rows x 1024
            const __half* Wx = g_Wih1h + (size_t)cg * 64 * HID;
            const __half* Wh = g_Whh1h + (size_t)cg * 64 * HID;
#pragma unroll 4
            for (int idx = tid; idx < 64 * 128; idx += NT_SCAN) {
                int n = idx >> 7, q = idx & 127;
                const __half* src = (q < 64) ? (Wx + (size_t)n * HID + q * 8)
                                             : (Wh + (size_t)n * HID + (q - 64) * 8);
                *(float4*)(Ws1 + n * W1PADH + q * 8) = *(const float4*)src;
            }
        }

        const float4 bias0 = *(const float4*)(g_biasP[1] + cg * 64 + gc0);
        const float4 bias1 = *(const float4*)(g_biasP[1] + cg * 64 + gc1);
        float cst0 = 0.0f, cst1 = 0.0f;

        grid_barrier_round(++round, 0);

        for (int r = 0; r < SEQ + 1; r++) {
            if (r >= 1) {
                const int t = r - 1;
                const __half* h0read = g_h0ring[t & 3];        // h0[t]
                const __half* h1read = g_hbuf1[t & 1];         // h1[t-1]
                __half*       hwrite = g_hbuf1[(t & 1) ^ 1];

                {   // warp-local stage: rows bg*32+mh*16..+16, concat cols kq*256..+256
                    const __half* src = (kq < 2) ? h0read : h1read;
                    const int kc = (kq & 1) * 256;
                    const __half* s = src + (size_t)(bg * 32 + mh * 16) * HID + kc;
                    __half* dst = As1 + (mh * 16) * W1PADH + kq * 256;
#pragma unroll
                    for (int i = 0; i < 16; i++) {
                        int idx = lane + 32 * i;
                        int row = idx >> 5, c8 = idx & 31;
                        *(float4*)(dst + row * W1PADH + c8 * 8) =
                            __ldcg((const float4*)(s + (size_t)row * HID + c8 * 8));
                    }
                }
                __syncwarp();

                // warp tile: 16(m) x 64(n), K=256
                wmma::fragment<wmma::accumulator, 16, 16, 16, float> acc[4];
#pragma unroll
                for (int j = 0; j < 4; j++) wmma::fill_fragment(acc[j], 0.0f);

                const __half* Abase = As1 + (mh * 16) * W1PADH + kq * 256;
                const __half* Bbase = Ws1 + kq * 256;
#pragma unroll
                for (int ks = 0; ks < 16; ks++) {
                    wmma::fragment<wmma::matrix_a, 16, 16, 16, __half, wmma::row_major> af;
                    wmma::fragment<wmma::matrix_b, 16, 16, 16, __half, wmma::col_major> bf[4];
                    wmma::load_matrix_sync(af, Abase + ks * 16, W1PADH);
#pragma unroll
                    for (int j = 0; j < 4; j++)
                        wmma::load_matrix_sync(bf[j], Bbase + j * 16 * W1PADH + ks * 16, W1PADH);
#pragma unroll
                    for (int j = 0; j < 4; j++) wmma::mma_sync(acc[j], af, bf[j], acc[j]);
                }
                __syncthreads();   // all warps done reading As1 before sg (alias) write
#pragma unroll
                for (int j = 0; j < 4; j++)
                    wmma::store_matrix_sync(&sg[kq * (32 * SGP1) + (mh * 16) * SGP1 + j * 16],
                                            acc[j], SGP1, wmma::mem_row_major);
                __syncthreads();

                {
                    float4 s0 = *(const float4*)&sg[0 * (32 * SGP1) + b0l * SGP1 + gc0];
                    float4 s1 = *(const float4*)&sg[1 * (32 * SGP1) + b0l * SGP1 + gc0];
                    float4 s2 = *(const float4*)&sg[2 * (32 * SGP1) + b0l * SGP1 + gc0];
                    float4 s3 = *(const float4*)&sg[3 * (32 * SGP1) + b0l * SGP1 + gc0];
                    float pi = s0.x + s1.x + s2.x + s3.x + bias0.x;
                    float pf = s0.y + s1.y + s2.y + s3.y + bias0.y;
                    float pg = s0.z + s1.z + s2.z + s3.z + bias0.z;
                    float po = s0.w + s1.w + s2.w + s3.w + bias0.w;
                    float ig = sigm(pi), fg = sigm(pf), gg = tanhf(pg), og = sigm(po);
                    cst0 = fg * cst0 + ig * gg;
                    hwrite[gb0 * HID + u0] = __float2half(og * tanhf(cst0));
                }
                {
                    float4 s0 = *(const float4*)&sg[0 * (32 * SGP1) + b1l * SGP1 + gc1];
                    float4 s1 = *(const float4*)&sg[1 * (32 * SGP1) + b1l * SGP1 + gc1];
                    float4 s2 = *(const float4*)&sg[2 * (32 * SGP1) + b1l * SGP1 + gc1];
                    float4 s3 = *(const float4*)&sg[3 * (32 * SGP1) + b1l * SGP1 + gc1];
                    float pi = s0.x + s1.x + s2.x + s3.x + bias1.x;
                    float pf = s0.y + s1.y + s2.y + s3.y + bias1.y;
                    float pg = s0.z + s1.z + s2.z + s3.z + bias1.z;
                    float po = s0.w + s1.w + s2.w + s3.w + bias1.w;
                    float ig = sigm(pi), fg = sigm(pf), gg = tanhf(pg), og = sigm(po);
                    cst1 = fg * cst1 + ig * gg;
                    hwrite[gb1 * HID + u1] = __float2half(og * tanhf(cst1));
                }
            }
            grid_barrier_round(++round, 0);
        }
    }
}

// ---------------- output projection (256 CTAs, 8-way split-K) ----------------
__global__ void out_kernel(const float* __restrict__ Wout, const float* __restrict__ bout,
                           float* __restrict__ out)
{
    __shared__ float red[256];
    int b  = blockIdx.y;
    int o  = blockIdx.x * 32 + (threadIdx.x & 31);
    int kq = threadIdx.x >> 5;     // 8-way split over 512 elems
    const __half2* h2 = (const __half2*)(g_hbuf1[0] + b * HID) + kq * 32;   // final h1 (t=511 odd -> buf 0)
    const float2*  w2 = (const float2*)(Wout + (size_t)o * HID) + kq * 32;
    float acc = 0.0f;
#pragma unroll
    for (int i = 0; i < 32; i++) {
        float2 hh = __half22float2(h2[i]);
        float2 ww = w2[i];
        acc += hh.x * ww.x + hh.y * ww.y;
    }
    red[threadIdx.x] = acc;
    __syncthreads();
    if (threadIdx.x < 32) {
        float s = bout[o];
#pragma unroll
        for (int k2 = 0; k2 < 8; k2++) s += red[threadIdx.x + 32 * k2];
        out[b * ODIM + o] = s;
    }
}

// ---------------- launch ----------------
extern "C" void kernel_launch(void* const* d_in, const int* in_sizes, int n_in,
                              void* d_out, int out_size)
{
    (void)in_sizes; (void)n_in; (void)out_size;
    const float* prim = (const float*)d_in[0];
    const float* aux  = (const float*)d_in[1];
    const float* Wih0 = (const float*)d_in[2];
    const float* Whh0 = (const float*)d_in[3];
    const float* bih0 = (const float*)d_in[4];
    const float* bhh0 = (const float*)d_in[5];
    const float* Wih1 = (const float*)d_in[6];
    const float* Whh1 = (const float*)d_in[7];
    const float* bih1 = (const float*)d_in[8];
    const float* bhh1 = (const float*)d_in[9];
    const float* Wout = (const float*)d_in[10];
    const float* bout = (const float*)d_in[11];
    float* out = (float*)d_out;

    static bool attr_set = false;
    if (!attr_set) {
        cudaFuncSetAttribute(scan_fused, cudaFuncAttributeMaxDynamicSharedMemorySize,
                             SCAN_SMEM_BYTES);
        attr_set = true;
    }

    prep_kernel<<<1024, 256>>>(prim, aux, Wih0, Whh0, bih0, bhh0, Wih1, Whh1, bih1, bhh1);
    gemm_tf32<<<dim3(16, 256), 256>>>();                      // x_proj0
    scan_fused<<<NB_SCAN, NT_SCAN, SCAN_SMEM_BYTES>>>();      // both layers, lag-2 decoupled
    out_kernel<<<dim3(4, BATCH), 256>>>(Wout, bout, out);
}

// round 17
// speedup vs baseline: 1.0997x; 1.0010x over previous
#include <cuda_runtime.h>
#include <cuda_bf16.h>
#include <cuda_fp16.h>
#include <mma.h>

using namespace nvcuda;

#define BATCH 64
#define SEQ   512
#define HID   512
#define GATES 2048
#define KIN   96
#define ODIM  128

#define NB_SCAN 128     // 64 layer-0 CTAs + 64 layer-1 CTAs
#define NT_SCAN 256
#define APADH   520     // 512+8 halfs
#define W1PADH  1032    // 1024+8 halfs
#define SGP0    64      // L0 sg stride (floats)
#define SGP1    68      // L1 sg stride (floats)
#define L0_TOTAL_B   ((32 + 64) * APADH * 2)           // 99,840
#define L1_TOTAL_B   ((64 + 32) * W1PADH * 2)          // 198,144
#define SCAN_SMEM_BYTES L1_TOTAL_B                     // 198,144 B (< 227 KB)

// ---------------- static device scratch ----------------
__device__ float  g_xproj[(size_t)BATCH * SEQ * GATES];
__device__ float  g_xcat[(size_t)BATCH * SEQ * KIN];
__device__ float  g_Wih0p[GATES * KIN];
__device__ __half g_Whh0h[GATES * HID];
__device__ __half g_Wih1h[GATES * HID];
__device__ __half g_Whh1h[GATES * HID];
__device__ float  g_biasP[2][GATES];
__device__ __half g_h0ring[4][BATCH * HID];  // h0[t] in ring[t&3]; ring[3] = h0[-1] = zeros
__device__ __half g_hbuf1[2][BATCH * HID];
__device__ unsigned g_flags[NB_SCAN][32];    // per-CTA round flags, 128B apart

// ---------------- sync primitives ----------------
__device__ __forceinline__ unsigned ld_acquire_gpu(const unsigned* p) {
    unsigned v;
    asm volatile("ld.acquire.gpu.global.u32 %0, [%1];" : "=r"(v) : "l"(p) : "memory");
    return v;
}
__device__ __forceinline__ void st_release_gpu(unsigned* p, unsigned v) {
    asm volatile("st.release.gpu.global.u32 [%0], %1;" :: "l"(p), "r"(v) : "memory");
}

// all-to-all flag barrier with group lag.
// lag_l1: this CTA only requires L1-group flags >= round - lag_l1 (L0 uses 2; L1 uses 0).
// Monotone thresholds -> deadlock-free; monotonic rounds -> graph-replay safe.
__device__ __forceinline__ void grid_barrier_round(unsigned round, unsigned lag_l1) {
    __syncthreads();
    if (threadIdx.x < 32) {
        if (threadIdx.x == 0)
            st_release_gpu(&g_flags[blockIdx.x][0], round);
        const int lane = threadIdx.x;
        bool ok;
        do {
            ok = true;
#pragma unroll
            for (int i = 0; i < NB_SCAN / 32; i++) {
                int cta = lane + 32 * i;
                unsigned tgt = round - ((cta >> 6) ? lag_l1 : 0u);
                unsigned f = ld_acquire_gpu(&g_flags[cta][0]);
                ok &= ((int)(f - tgt) >= 0);
            }
        } while (!__all_sync(0xffffffffu, ok));
    }
    __syncthreads();
}

__device__ __forceinline__ float sigm(float x) { return 1.0f / (1.0f + expf(-x)); }

__device__ __forceinline__ float tf32_rna(float x) {
    unsigned u;
    asm("cvt.rna.tf32.f32 %0, %1;" : "=r"(u) : "f"(x));
    return __uint_as_float(u);
}

// ---------------- prep ----------------
__global__ void prep_kernel(const float* __restrict__ prim, const float* __restrict__ aux,
                            const float* __restrict__ Wih0, const float* __restrict__ Whh0,
                            const float* __restrict__ bih0, const float* __restrict__ bhh0,
                            const float* __restrict__ Wih1, const float* __restrict__ Whh1,
                            const float* __restrict__ bih1, const float* __restrict__ bhh1)
{
    size_t tid = (size_t)blockIdx.x * blockDim.x + threadIdx.x;
    size_t nth = (size_t)gridDim.x * blockDim.x;

    for (size_t i = tid; i < (size_t)BATCH * SEQ * KIN; i += nth) {
        int k = (int)(i % KIN);
        size_t bt = i / KIN;
        int b = (int)(bt / SEQ);
        g_xcat[i] = tf32_rna((k < 64) ? prim[bt * 64 + k] : aux[b * 32 + (k - 64)]);
    }
    for (size_t i = tid; i < (size_t)GATES * HID; i += nth) {
        int k  = (int)(i % HID);
        int cp = (int)(i / HID);
        int u = cp >> 2, gi = cp & 3;
        size_t r = (size_t)(gi * HID + u) * HID + k;
        g_Whh0h[i] = __float2half(Whh0[r]);
        g_Whh1h[i] = __float2half(Whh1[r]);
        g_Wih1h[i] = __float2half(Wih1[r]);
    }
    for (size_t i = tid; i < (size_t)GATES * KIN; i += nth) {
        int k  = (int)(i % KIN);
        int cp = (int)(i / KIN);
        int u = cp >> 2, gi = cp & 3;
        g_Wih0p[i] = tf32_rna(Wih0[(size_t)(gi * HID + u) * KIN + k]);
    }
    for (size_t i = tid; i < GATES; i += nth) {
        int u = (int)(i >> 2), gi = (int)(i & 3);
        int r = gi * HID + u;
        g_biasP[0][i] = bih0[r] + bhh0[r];
        g_biasP[1][i] = bih1[r] + bhh1[r];
    }
}

// ---------------- x_proj0 GEMM (tf32 wmma) ----------------
#define GT_M 128
#define GT_N 128
#define KCHUNK 16
#define SPAD 20

__global__ void __launch_bounds__(256) gemm_tf32()
{
    __shared__ float As[GT_M * SPAD];
    __shared__ float Bs[GT_N * SPAD];

    const float* A  = g_xcat;
    const float* Bm = g_Wih0p;
    const int K     = KIN;

    int tn = blockIdx.x;
    int tm = blockIdx.y;
    int tid = threadIdx.x;
    int wid = tid >> 5;
    int wm = wid >> 2, wn = wid & 3;

    wmma::fragment<wmma::accumulator, 16, 16, 8, float> acc[4][2];
#pragma unroll
    for (int i = 0; i < 4; i++)
#pragma unroll
        for (int j = 0; j < 2; j++) wmma::fill_fragment(acc[i][j], 0.0f);

    const float* Abase = A  + (size_t)tm * GT_M * K;
    const float* Bbase = Bm + (size_t)tn * GT_N * K;

    for (int k0 = 0; k0 < K; k0 += KCHUNK) {
        __syncthreads();
#pragma unroll
        for (int s = tid; s < GT_M * 4; s += 256) {
            int m = s >> 2, q = s & 3;
            *(float4*)&As[m * SPAD + q * 4] = *(const float4*)&Abase[(size_t)m * K + k0 + q * 4];
            *(float4*)&Bs[m * SPAD + q * 4] = *(const float4*)&Bbase[(size_t)m * K + k0 + q * 4];
        }
        __syncthreads();
#pragma unroll
        for (int ks = 0; ks < 2; ks++) {
            wmma::fragment<wmma::matrix_b, 16, 16, 8, wmma::precision::tf32, wmma::col_major> bf[2];
#pragma unroll
            for (int j = 0; j < 2; j++)
                wmma::load_matrix_sync(bf[j], &Bs[(wn * 32 + j * 16) * SPAD + ks * 8], SPAD);
#pragma unroll
            for (int i = 0; i < 4; i++) {
                wmma::fragment<wmma::matrix_a, 16, 16, 8, wmma::precision::tf32, wmma::row_major> af;
                wmma::load_matrix_sync(af, &As[(wm * 64 + i * 16) * SPAD + ks * 8], SPAD);
#pragma unroll
                for (int j = 0; j < 2; j++) wmma::mma_sync(acc[i][j], af, bf[j], acc[i][j]);
            }
        }
    }
#pragma unroll
    for (int i = 0; i < 4; i++)
#pragma unroll
        for (int j = 0; j < 2; j++) {
            int gm = tm * GT_M + wm * 64 + i * 16;
            int gn = tn * GT_N + wn * 32 + j * 16;
            wmma::store_matrix_sync(&g_xproj[(size_t)gm * GATES + gn], acc[i][j], GATES,
                                    wmma::mem_row_major);
        }
}

// ---------------- fused dual-layer persistent scan (lag-2 decoupled) ----------------
// 64 CTAs/group = 32 gate-groups (64 cols) x 2 batch-groups (32 rows).
__global__ void __launch_bounds__(NT_SCAN) scan_fused()
{
    extern __shared__ char smem_raw[];

    const int tid  = threadIdx.x;
    const int w    = tid >> 5;
    const int lane = tid & 31;
    const int grp  = blockIdx.x >> 6;          // 0 = layer0, 1 = layer1
    const int c    = blockIdx.x & 63;
    const int bg   = c & 1;                    // batch group: rows [bg*32, +32)
    const int cg   = c >> 1;                   // gate group: cols [cg*64, +64)

    const int mh = w & 1;                      // 16-row half of the 32-row batch slice
    const int kq = w >> 1;                     // k quarter

    const __half hzero = __float2half(0.0f);
    // group-local zero-init: L0 group zeros ring[3] (h0[-1]); L1 group zeros h1buf[0].
    // Each consumer's barrier wait covers its producer group.
    if (grp == 0) {
        for (int i = c * NT_SCAN + tid; i < BATCH * HID; i += 64 * NT_SCAN)
            g_h0ring[3][i] = hzero;
    } else {
        for (int i = c * NT_SCAN + tid; i < BATCH * HID; i += 64 * NT_SCAN)
            g_hbuf1[0][i] = hzero;
    }

    unsigned round = ld_acquire_gpu(&g_flags[blockIdx.x][0]);

    // elementwise mapping: 2 outputs/thread over 32 b x 16 units
    const int p0 = tid,            b0l = p0 >> 4, ul0 = p0 & 15, gc0 = ul0 * 4;
    const int p1 = tid + NT_SCAN,  b1l = p1 >> 4, ul1 = p1 & 15, gc1 = ul1 * 4;
    const int gb0 = bg * 32 + b0l, gb1 = bg * 32 + b1l;
    const int u0 = cg * 16 + ul0,  u1 = cg * 16 + ul1;

    if (grp == 0) {
        // ---------------- layer 0 (runs up to 2 rounds ahead) ----------------
        __half* As = (__half*)smem_raw;             // [32][APADH]
        __half* Ws = As + 32 * APADH;               // [64][APADH]
        float*  sg = (float*)smem_raw;              // alias: [4][32][SGP0]

        {   // stage W slice once: 64 gate rows x 512
            const __half* Wg = g_Whh0h + (size_t)cg * 64 * HID;
#pragma unroll 4
            for (int idx = tid; idx < 64 * 64; idx += NT_SCAN) {
                int n = idx >> 6, q = idx & 63;
                *(float4*)(Ws + n * APADH + q * 8) = *(const float4*)(Wg + (size_t)n * HID + q * 8);
            }
        }

        const float4 bias0 = *(const float4*)(g_biasP[0] + cg * 64 + gc0);
        const float4 bias1 = *(const float4*)(g_biasP[0] + cg * 64 + gc1);
        const float* xpp0 = g_xproj + (size_t)gb0 * SEQ * GATES + cg * 64 + gc0;
        const float* xpp1 = g_xproj + (size_t)gb1 * SEQ * GATES + cg * 64 + gc1;
        float cst0 = 0.0f, cst1 = 0.0f;

        grid_barrier_round(++round, 2);

        float4 xp0 = __ldcs((const float4*)xpp0);
        float4 xp1 = __ldcs((const float4*)xpp1);

        for (int r = 0; r < SEQ + 1; r++) {
            if (r < SEQ) {
                const int t = r;
                const __half* hread  = g_h0ring[(t + 3) & 3];   // h0[t-1]
                __half*       hwrite = g_h0ring[t & 3];         // h0[t] (overwrites h0[t-4])

                {   // warp-local stage: rows bg*32+mh*16..+16, cols kq*128..+128 (8 f4/lane)
                    const __half* src = hread + (size_t)(bg * 32 + mh * 16) * HID + kq * 128;
                    __half* dst = As + (mh * 16) * APADH + kq * 128;
#pragma unroll
                    for (int i = 0; i < 8; i++) {
                        int idx = lane + 32 * i;
                        int row = idx >> 4, c8 = idx & 15;
                        *(float4*)(dst + row * APADH + c8 * 8) =
                            __ldcg((const float4*)(src + (size_t)row * HID + c8 * 8));
                    }
                }
                __syncwarp();

                // warp tile: 16(m) x 64(n), K=128
                wmma::fragment<wmma::accumulator, 16, 16, 16, float> acc[4];
#pragma unroll
                for (int j = 0; j < 4; j++) wmma::fill_fragment(acc[j], 0.0f);

                const __half* Abase = As + (mh * 16) * APADH + kq * 128;
                const __half* Bbase = Ws + kq * 128;
#pragma unroll
                for (int ks = 0; ks < 8; ks++) {
                    wmma::fragment<wmma::matrix_a, 16, 16, 16, __half, wmma::row_major> af;
                    wmma::fragment<wmma::matrix_b, 16, 16, 16, __half, wmma::col_major> bf[4];
                    wmma::load_matrix_sync(af, Abase + ks * 16, APADH);
#pragma unroll
                    for (int j = 0; j < 4; j++)
                        wmma::load_matrix_sync(bf[j], Bbase + j * 16 * APADH + ks * 16, APADH);
#pragma unroll
                    for (int j = 0; j < 4; j++) wmma::mma_sync(acc[j], af, bf[j], acc[j]);
                }
                __syncthreads();   // all warps done reading As before sg (alias) write
#pragma unroll
                for (int j = 0; j < 4; j++)
                    wmma::store_matrix_sync(&sg[kq * (32 * SGP0) + (mh * 16) * SGP0 + j * 16],
                                            acc[j], SGP0, wmma::mem_row_major);
                __syncthreads();

                {
                    float4 s0 = *(const float4*)&sg[0 * (32 * SGP0) + b0l * SGP0 + gc0];
                    float4 s1 = *(const float4*)&sg[1 * (32 * SGP0) + b0l * SGP0 + gc0];
                    float4 s2 = *(const float4*)&sg[2 * (32 * SGP0) + b0l * SGP0 + gc0];
                    float4 s3 = *(const float4*)&sg[3 * (32 * SGP0) + b0l * SGP0 + gc0];
                    float pi = s0.x + s1.x + s2.x + s3.x + xp0.x + bias0.x;
                    float pf = s0.y + s1.y + s2.y + s3.y + xp0.y + bias0.y;
                    float pg = s0.z + s1.z + s2.z + s3.z + xp0.z + bias0.z;
                    float po = s0.w + s1.w + s2.w + s3.w + xp0.w + bias0.w;
                    float ig = sigm(pi), fg = sigm(pf), gg = tanhf(pg), og = sigm(po);
                    cst0 = fg * cst0 + ig * gg;
                    hwrite[gb0 * HID + u0] = __float2half(og * tanhf(cst0));
                }
                {
                    float4 s0 = *(const float4*)&sg[0 * (32 * SGP0) + b1l * SGP0 + gc1];
                    float4 s1 = *(const float4*)&sg[1 * (32 * SGP0) + b1l * SGP0 + gc1];
                    float4 s2 = *(const float4*)&sg[2 * (32 * SGP0) + b1l * SGP0 + gc1];
                    float4 s3 = *(const float4*)&sg[3 * (32 * SGP0) + b1l * SGP0 + gc1];
                    float pi = s0.x + s1.x + s2.x + s3.x + xp1.x + bias1.x;
                    float pf = s0.y + s1.y + s2.y + s3.y + xp1.y + bias1.y;
                    float pg = s0.z + s1.z + s2.z + s3.z + xp1.z + bias1.z;
                    float po = s0.w + s1.w + s2.w + s3.w + xp1.w + bias1.w;
                    float ig = sigm(pi), fg = sigm(pf), gg = tanhf(pg), og = sigm(po);
                    cst1 = fg * cst1 + ig * gg;
                    hwrite[gb1 * HID + u1] = __float2half(og * tanhf(cst1));
                }
                int tn2 = (t + 1 < SEQ) ? (t + 1) : (SEQ - 1);
                xp0 = __ldcs((const float4*)(xpp0 + (size_t)tn2 * GATES));
                xp1 = __ldcs((const float4*)(xpp1 + (size_t)tn2 * GATES));
            }
            grid_barrier_round(++round, 2);
        }
    } else {
        // ---------------- layer 1 (lag 1 behind L0) ----------------
        __half* Ws1 = (__half*)smem_raw;            // [64][W1PADH]
        __half* As1 = Ws1 + 64 * W1PADH;            // [32][W1PADH]
        float*  sg  = (float*)As1;                  // alias: [4][32][SGP1]

        {   // stage concat W once: 64 gate rows x 1024
            const __half* Wx = g_Wih1h + (size_t)cg * 64 * HID;
            const __half* Wh = g_Whh1h + (size_t)cg * 64 * HID;
#pragma unroll 4
            for (int idx = tid; idx < 64 * 128; idx += NT_SCAN) {
                int n = idx >> 7, q = idx & 127;
                const __half* src = (q < 64) ? (Wx + (size_t)n * HID + q * 8)
                                             : (Wh + (size_t)n * HID + (q - 64) * 8);
                *(float4*)(Ws1 + n * W1PADH + q * 8) = *(const float4*)src;
            }
        }

        const float4 bias0 = *(const float4*)(g_biasP[1] + cg * 64 + gc0);
        const float4 bias1 = *(const float4*)(g_biasP[1] + cg * 64 + gc1);
        float cst0 = 0.0f, cst1 = 0.0f;

        grid_barrier_round(++round, 0);

        for (int r = 0; r < SEQ + 1; r++) {
            if (r >= 1) {
                const int t = r - 1;
                const __half* h0read = g_h0ring[t & 3];        // h0[t]
                const __half* h1read = g_hbuf1[t & 1];         // h1[t-1]
                __half*       hwrite = g_hbuf1[(t & 1) ^ 1];

                {   // warp-local stage: rows bg*32+mh*16..+16, concat cols kq*256..+256
                    const __half* src = (kq < 2) ? h0read : h1read;
                    const int kc = (kq & 1) * 256;
                    const __half* s = src + (size_t)(bg * 32 + mh * 16) * HID + kc;
                    __half* dst = As1 + (mh * 16) * W1PADH + kq * 256;
#pragma unroll
                    for (int i = 0; i < 16; i++) {
                        int idx = lane + 32 * i;
                        int row = idx >> 5, c8 = idx & 31;
                        *(float4*)(dst + row * W1PADH + c8 * 8) =
                            __ldcg((const float4*)(s + (size_t)row * HID + c8 * 8));
                    }
                }
                __syncwarp();

                // warp tile: 16(m) x 64(n), K=256
                wmma::fragment<wmma::accumulator, 16, 16, 16, float> acc[4];
#pragma unroll
                for (int j = 0; j < 4; j++) wmma::fill_fragment(acc[j], 0.0f);

                const __half* Abase = As1 + (mh * 16) * W1PADH + kq * 256;
                const __half* Bbase = Ws1 + kq * 256;
#pragma unroll
                for (int ks = 0; ks < 16; ks++) {
                    wmma::fragment<wmma::matrix_a, 16, 16, 16, __half, wmma::row_major> af;
                    wmma::fragment<wmma::matrix_b, 16, 16, 16, __half, wmma::col_major> bf[4];
                    wmma::load_matrix_sync(af, Abase + ks * 16, W1PADH);
#pragma unroll
                    for (int j = 0; j < 4; j++)
                        wmma::load_matrix_sync(bf[j], Bbase + j * 16 * W1PADH + ks * 16, W1PADH);
#pragma unroll
                    for (int j = 0; j < 4; j++) wmma::mma_sync(acc[j], af, bf[j], acc[j]);
                }
                __syncthreads();   // all warps done reading As1 before sg (alias) write
#pragma unroll
                for (int j = 0; j < 4; j++)
                    wmma::store_matrix_sync(&sg[kq * (32 * SGP1) + (mh * 16) * SGP1 + j * 16],
                                            acc[j], SGP1, wmma::mem_row_major);
                __syncthreads();

                {
                    float4 s0 = *(const float4*)&sg[0 * (32 * SGP1) + b0l * SGP1 + gc0];
                    float4 s1 = *(const float4*)&sg[1 * (32 * SGP1) + b0l * SGP1 + gc0];
                    float4 s2 = *(const float4*)&sg[2 * (32 * SGP1) + b0l * SGP1 + gc0];
                    float4 s3 = *(const float4*)&sg[3 * (32 * SGP1) + b0l * SGP1 + gc0];
                    float pi = s0.x + s1.x + s2.x + s3.x + bias0.x;
                    float pf = s0.y + s1.y + s2.y + s3.y + bias0.y;
                    float pg = s0.z + s1.z + s2.z + s3.z + bias0.z;
                    float po = s0.w + s1.w + s2.w + s3.w + bias0.w;
                    float ig = sigm(pi), fg = sigm(pf), gg = tanhf(pg), og = sigm(po);
                    cst0 = fg * cst0 + ig * gg;
                    hwrite[gb0 * HID + u0] = __float2half(og * tanhf(cst0));
                }
                {
                    float4 s0 = *(const float4*)&sg[0 * (32 * SGP1) + b1l * SGP1 + gc1];
                    float4 s1 = *(const float4*)&sg[1 * (32 * SGP1) + b1l * SGP1 + gc1];
                    float4 s2 = *(const float4*)&sg[2 * (32 * SGP1) + b1l * SGP1 + gc1];
                    float4 s3 = *(const float4*)&sg[3 * (32 * SGP1) + b1l * SGP1 + gc1];
                    float pi = s0.x + s1.x + s2.x + s3.x + bias1.x;
                    float pf = s0.y + s1.y + s2.y + s3.y + bias1.y;
                    float pg = s0.z + s1.z + s2.z + s3.z + bias1.z;
                    float po = s0.w + s1.w + s2.w + s3.w + bias1.w;
                    float ig = sigm(pi), fg = sigm(pf), gg = tanhf(pg), og = sigm(po);
                    cst1 = fg * cst1 + ig * gg;
                    hwrite[gb1 * HID + u1] = __float2half(og * tanhf(cst1));
                }
            }
            grid_barrier_round(++round, 0);
        }
    }
}

// ---------------- output projection (256 CTAs, 8-way split-K) ----------------
__global__ void out_kernel(const float* __restrict__ Wout, const float* __restrict__ bout,
                           float* __restrict__ out)
{
    __shared__ float red[256];
    int b  = blockIdx.y;
    int o  = blockIdx.x * 32 + (threadIdx.x & 31);
    int kq = threadIdx.x >> 5;     // 8-way split over 512 elems
    const __half2* h2 = (const __half2*)(g_hbuf1[0] + b * HID) + kq * 32;   // final h1 (t=511 odd -> buf 0)
    const float2*  w2 = (const float2*)(Wout + (size_t)o * HID) + kq * 32;
    float acc = 0.0f;
#pragma unroll
    for (int i = 0; i < 32; i++) {
        float2 hh = __half22float2(h2[i]);
        float2 ww = w2[i];
        acc += hh.x * ww.x + hh.y * ww.y;
    }
    red[threadIdx.x] = acc;
    __syncthreads();
    if (threadIdx.x < 32) {
        float s = bout[o];
#pragma unroll
        for (int k2 = 0; k2 < 8; k2++) s += red[threadIdx.x + 32 * k2];
        out[b * ODIM + o] = s;
    }
}

// ---------------- launch ----------------
extern "C" void kernel_launch(void* const* d_in, const int* in_sizes, int n_in,
                              void* d_out, int out_size)
{
    (void)in_sizes; (void)n_in; (void)out_size;
    const float* prim = (const float*)d_in[0];
    const float* aux  = (const float*)d_in[1];
    const float* Wih0 = (const float*)d_in[2];
    const float* Whh0 = (const float*)d_in[3];
    const float* bih0 = (const float*)d_in[4];
    const float* bhh0 = (const float*)d_in[5];
    const float* Wih1 = (const float*)d_in[6];
    const float* Whh1 = (const float*)d_in[7];
    const float* bih1 = (const float*)d_in[8];
    const float* bhh1 = (const float*)d_in[9];
    const float* Wout = (const float*)d_in[10];
    const float* bout = (const float*)d_in[11];
    float* out = (float*)d_out;

    static bool attr_set = false;
    if (!attr_set) {
        cudaFuncSetAttribute(scan_fused, cudaFuncAttributeMaxDynamicSharedMemorySize,
                             SCAN_SMEM_BYTES);
        attr_set = true;
    }

    prep_kernel<<<1024, 256>>>(prim, aux, Wih0, Whh0, bih0, bhh0, Wih1, Whh1, bih1, bhh1);
    gemm_tf32<<<dim3(16, 256), 256>>>();                      // x_proj0
    scan_fused<<<NB_SCAN, NT_SCAN, SCAN_SMEM_BYTES>>>();      // both layers, lag-2 decoupled
    out_kernel<<<dim3(4, BATCH), 256>>>(Wout, bout, out);
}